// round 13
// baseline (speedup 1.0000x reference)
#include <cuda_runtime.h>
#include <cstdint>

#define NN 50000
#define NE 800000
#define NG 256
#define NTILE2 12500        // NE / 64
#define PGRID 152

typedef unsigned long long ull;

// TAU16: within 16-blocks, col (8a+2t+b) -> pos (4t+2a+b)
__host__ __device__ __forceinline__ int TAU16(int c) {
    int j = c & 15;
    return (c & ~15) | (((j >> 1) & 3) << 2) | (((j >> 3) & 1) << 1) | (j & 1);
}

// ---------------- fp16 mma.sync helpers ----------------
__device__ __forceinline__ uint32_t f2h2(float lo, float hi) {
    uint32_t r; asm("cvt.rn.f16x2.f32 %0, %1, %2;" : "=r"(r) : "f"(hi), "f"(lo)); return r;
}
__device__ __forceinline__ void mma16(float* d, const uint32_t* a, uint32_t b0, uint32_t b1) {
    asm volatile("mma.sync.aligned.m16n8k16.row.col.f32.f16.f16.f32 "
        "{%0,%1,%2,%3},{%4,%5,%6,%7},{%8,%9},{%0,%1,%2,%3};"
        : "+f"(d[0]), "+f"(d[1]), "+f"(d[2]), "+f"(d[3])
        : "r"(a[0]), "r"(a[1]), "r"(a[2]), "r"(a[3]), "r"(b0), "r"(b1));
}

// ---------------- f32x2 helpers ----------------
__device__ __forceinline__ void ffma2(ull &d, ull a, ull b) {
    asm("fma.rn.f32x2 %0, %1, %2, %0;" : "+l"(d) : "l"(a), "l"(b));
}
__device__ __forceinline__ ull pack2(float lo, float hi) {
    ull r; asm("mov.b64 %0, {%1, %2};" : "=l"(r) : "f"(lo), "f"(hi)); return r;
}
__device__ __forceinline__ float2 unpack2(ull v) {
    float2 r; asm("mov.b64 {%0, %1}, %2;" : "=f"(r.x), "=f"(r.y) : "l"(v)); return r;
}
__device__ __forceinline__ ull relu2(ull v) {
    float2 t = unpack2(v);
    return pack2(fmaxf(t.x, 0.f), fmaxf(t.y, 0.f));
}
__device__ __forceinline__ void red_add_v4f(float* p, float a, float b, float c, float d) {
    asm volatile("red.global.add.v4.f32 [%0], {%1,%2,%3,%4};" :: "l"(p), "f"(a), "f"(b), "f"(c), "f"(d) : "memory");
}
__device__ __forceinline__ void red_add_f(float* p, float a) {
    asm volatile("red.global.add.f32 [%0], %1;" :: "l"(p), "f"(a) : "memory");
}

// ---------------- device scratch ----------------
__device__ float d_P [NN*128];   // (x@e_w1[:64] + Rg[batch] + eb1), TAU16 layout
__device__ float d_Q [NN*128];   // TAU16 layout
__device__ float d_Ms[NN*128];   // TAU16 layout
__device__ float d_Rg[NG*128];   // natural layout
__device__ float d_agg[NN*128];  // TAU16 layout
__device__ float d_deg[NN];
__device__ float d_gsum[NG*64];
__device__ float d_gcnt[NG];

// ---------------- K0 / K0b ----------------
__global__ void k_zero() {
    int i = blockIdx.x * blockDim.x + threadIdx.x;
    int stride = gridDim.x * blockDim.x;
    for (int idx = i; idx < NN*128; idx += stride) d_agg[idx] = 0.f;
    for (int idx = i; idx < NN;     idx += stride) d_deg[idx] = 0.f;
    for (int idx = i; idx < NG*64;  idx += stride) d_gsum[idx] = 0.f;
    for (int idx = i; idx < NG;     idx += stride) d_gcnt[idx] = 0.f;
}
__global__ void k_count(const int* __restrict__ ei, const int* __restrict__ batch) {
    int i = blockIdx.x * blockDim.x + threadIdx.x;
    if (i < NE) atomicAdd(&d_deg[ei[NE + i]], 1.f);
    if (i < NN) atomicAdd(&d_gcnt[batch[i]], 1.f);
}

// ---------------- K1b: R = u @ e_w1[160:176] ----------------
__global__ void k_rg(const float* __restrict__ u, const float* __restrict__ ew1) {
    int i = blockIdx.x * blockDim.x + threadIdx.x;
    if (i < NG*128) {
        int g = i >> 7, j = i & 127;
        float acc = 0.f;
        #pragma unroll
        for (int k = 0; k < 16; k++) acc += u[g*16 + k] * ew1[(160 + k)*128 + j];
        d_Rg[i] = acc;
    }
}

// ---------------- K1: precompute PR, Q, Msrc (fp32-exact; TAU16 store) ----------------
#define PRE_SMEM ((4352 + 3*8192 + 256 + 64) * 4)
__global__ void __launch_bounds__(512, 1)
k_pre(const float* __restrict__ x, const float* __restrict__ ew1,
      const float* __restrict__ eb1, const float* __restrict__ n1w1,
      const float* __restrict__ n1b1, const int* __restrict__ batch) {
    extern __shared__ float sm[];
    float* sXT  = sm;
    float* sWa  = sm + 4352;
    float* sWb  = sWa + 8192;
    float* sWm  = sWb + 8192;
    float* sEb1 = sWm + 8192;
    float* sNb1 = sEb1 + 128;
    int*   sBat = (int*)(sNb1 + 128);
    int tid = threadIdx.x;
    for (int i = tid; i < 8192; i += 512) {
        sWa[i] = ew1[i];
        sWb[i] = ew1[64*128 + i];
        sWm[i] = n1w1[i];
    }
    if (tid < 128) { sEb1[tid] = eb1[tid]; sNb1[tid] = n1b1[tid]; }
    int n0 = blockIdx.x * 64;
    if (tid < 64) {
        int n = n0 + tid;
        sBat[tid] = (n < NN) ? batch[n] : 0;
    }
    for (int idx = tid; idx < 64*64; idx += 512) {
        int node = idx >> 6, k = idx & 63;
        int n = n0 + node;
        sXT[k*68 + node] = (n < NN) ? x[(size_t)n*64 + k] : 0.f;
    }
    __syncthreads();
    int tx = tid & 31, wid = tid >> 5;
    int ty = wid & 7, fh = wid >> 3;
    int fbase = fh*64 + tx*2;
    int fdst = TAU16(fbase);
    for (int which = 0; which < 3; which++) {
        const float* W = (which == 0) ? sWa : (which == 1) ? sWb : sWm;
        ull acc[4][2];
        #pragma unroll
        for (int p = 0; p < 4; p++)
            #pragma unroll
            for (int j = 0; j < 2; j++) {
                float b = (which == 0) ? sEb1[fbase + j] : (which == 2) ? sNb1[fbase + j] : 0.f;
                acc[p][j] = pack2(b, b);
            }
        #pragma unroll 4
        for (int k = 0; k < 64; k++) {
            float2 B = *(const float2*)&W[k*128 + fbase];
            ull bb0 = pack2(B.x, B.x), bb1 = pack2(B.y, B.y);
            float4 A0 = *(const float4*)&sXT[k*68 + ty*8];
            float4 A1 = *(const float4*)&sXT[k*68 + ty*8 + 4];
            ull a0 = pack2(A0.x, A0.y), a1 = pack2(A0.z, A0.w);
            ull a2 = pack2(A1.x, A1.y), a3 = pack2(A1.z, A1.w);
            ffma2(acc[0][0], a0, bb0); ffma2(acc[0][1], a0, bb1);
            ffma2(acc[1][0], a1, bb0); ffma2(acc[1][1], a1, bb1);
            ffma2(acc[2][0], a2, bb0); ffma2(acc[2][1], a2, bb1);
            ffma2(acc[3][0], a3, bb0); ffma2(acc[3][1], a3, bb1);
        }
        float* dst = (which == 0) ? d_P : (which == 1) ? d_Q : d_Ms;
        #pragma unroll
        for (int p = 0; p < 4; p++) {
            float2 v0 = unpack2(acc[p][0]), v1 = unpack2(acc[p][1]);
            int node = ty*8 + 2*p;
            int n_lo = n0 + node;
            if (which == 0) {
                if (n_lo < NN) {
                    const float* rg = &d_Rg[(size_t)sBat[node]*128 + fbase];
                    v0.x += rg[0]; v1.x += rg[1];
                }
                if (n_lo + 1 < NN) {
                    const float* rg = &d_Rg[(size_t)sBat[node+1]*128 + fbase];
                    v0.y += rg[0]; v1.y += rg[1];
                }
            }
            if (n_lo < NN)
                *(float2*)&dst[(size_t)n_lo*128 + fdst] = make_float2(v0.x, v1.x);
            if (n_lo + 1 < NN)
                *(float2*)&dst[(size_t)(n_lo+1)*128 + fdst] = make_float2(v0.y, v1.y);
        }
    }
}

// ================= K2: merged edge pipeline — 512 thr, 64-edge tiles, 2 CTAs/SM =================
// word layout: sW1p 2048 | sW2p 4096 | sW3p 4096 | sW4p 8192 |
//   sEA 1280 [e*20] | sEN 2304 [e*36] | sH 4352 [e*68] | sB2 64 | sB4 128 | idx 128
//   = 26688 words = 106,752 B  → 2 CTAs/SM
#define S2_SMEM (26688 * 4)
__global__ void __launch_bounds__(512, 2)
k2(const float* __restrict__ ea, const float* __restrict__ ew1,
   const float* __restrict__ ew2, const float* __restrict__ eb2,
   const float* __restrict__ n1w1, const float* __restrict__ n1w2,
   const float* __restrict__ n1b2,
   const int* __restrict__ ei, float* __restrict__ outE) {
    extern __shared__ float sm[];
    uint32_t* sW1p = (uint32_t*)sm;               // 2048
    uint32_t* sW2p = (uint32_t*)(sm + 2048);      // 4096
    uint32_t* sW3p = (uint32_t*)(sm + 6144);      // 4096
    uint32_t* sW4p = (uint32_t*)(sm + 10240);     // 8192
    uint32_t* sEA  = (uint32_t*)(sm + 18432);     // 1280  [e*20]
    uint32_t* sEN  = (uint32_t*)(sm + 19712);     // 2304  [e*36]
    uint32_t* sH   = (uint32_t*)(sm + 22016);     // 4352  [e*68]
    float*    sB2  = sm + 26368;                  // 64
    float*    sB4  = sm + 26432;                  // 128
    int* sRow = (int*)(sm + 26560);               // 64
    int* sCol = sRow + 64;                        // 64

    int tid = threadIdx.x, lane = tid & 31, w = tid >> 5;
    int wm = w & 3, wn = w >> 2;
    int g = lane >> 2, tig = lane & 3;
    int e1 = wm*16 + g, e2 = e1 + 8;

    // ---- W1c^T fp16 staging (2048 words) ----
    for (int i = tid; i < 2048; i += 512) {
        int q = i & 3, ln = (i >> 2) & 31, pr = (i >> 7) & 1;
        int s = (i >> 8) & 1, wn_ = (i >> 9) & 3;
        int gg = ln >> 2, tt = ln & 3;
        int nt = pr*2 + (q >> 1), hb = q & 1;
        int n = (wn_*4 + nt)*8 + gg;
        int k0 = s*16 + 2*tt + hb*8;
        sW1p[i] = f2h2(ew1[(128 + k0)*128 + n], ew1[(128 + k0 + 1)*128 + n]);
    }
    // ---- W2^T fp16 staging (4096 words) ----
    for (int i = tid; i < 4096; i += 512) {
        int q = i & 3, ln = (i >> 2) & 31;
        int s = (i >> 7) & 7, wn_ = (i >> 10) & 3;
        int gg = ln >> 2, tt = ln & 3;
        int nt = q >> 1, hb = q & 1;
        int n = (wn_*2 + nt)*8 + gg;
        int k0 = s*16 + 2*tt + hb*8;
        sW2p[i] = f2h2(ew2[k0*64 + n], ew2[(k0 + 1)*64 + n]);
    }
    // ---- W3^T fp16 staging (4096 words) ----
    for (int i = tid; i < 4096; i += 512) {
        int q = i & 3, ln = (i >> 2) & 31, pr = (i >> 7) & 1;
        int s = (i >> 8) & 3, wn_ = (i >> 10) & 3;
        int gg = ln >> 2, tt = ln & 3;
        int nt = pr*2 + (q >> 1), hb = q & 1;
        int n = (wn_*4 + nt)*8 + gg;
        int k0 = s*16 + 2*tt + hb*8;
        sW3p[i] = f2h2(n1w1[(64 + k0)*128 + n], n1w1[(64 + k0 + 1)*128 + n]);
    }
    // ---- W4^T fp16 staging (8192 words) ----
    for (int i = tid; i < 8192; i += 512) {
        int q = i & 3, ln = (i >> 2) & 31, pr = (i >> 7) & 1;
        int s = (i >> 8) & 7, wn_ = (i >> 11) & 3;
        int gg = ln >> 2, tt = ln & 3;
        int nt = pr*2 + (q >> 1), hb = q & 1;
        int n = (wn_*4 + nt)*8 + gg;
        int k0 = s*16 + 2*tt + hb*8;
        sW4p[i] = f2h2(n1w2[k0*128 + n], n1w2[(k0 + 1)*128 + n]);
    }
    if (tid < 64)  sB2[tid] = eb2[tid];
    if (tid < 128) sB4[tid] = n1b2[tid];

    for (int t = blockIdx.x; t < NTILE2; t += gridDim.x) {
        __syncthreads();     // previous-tile sH/sEN reads done
        int e0 = t * 64;
        if (tid < 64) {
            sRow[tid] = ei[e0 + tid];
            sCol[tid] = ei[NE + e0 + tid];
        }
        if (tid < 256) {     // stage EA [64][32] fp16 (coalesced)
            int e = tid >> 2, ch = tid & 3;
            float4 v0 = *(const float4*)&ea[(size_t)(e0 + e)*32 + ch*8];
            float4 v1 = *(const float4*)&ea[(size_t)(e0 + e)*32 + ch*8 + 4];
            *(uint4*)&sEA[e*20 + ch*4] = make_uint4(
                f2h2(v0.x, v0.y), f2h2(v0.z, v0.w), f2h2(v1.x, v1.y), f2h2(v1.z, v1.w));
        }
        __syncthreads();

        int r1 = sRow[e1], cc1 = sCol[e1];
        int r2 = sRow[e2], cc2 = sCol[e2];

        // ======== GEMM1: H1 = relu(PR[row] + Q[col] + EA @ W1c) ========
        float acc[4][4];
        {
            const float4* P1 = (const float4*)&d_P[(size_t)r1*128 + wn*32 + tig*4];
            const float4* Q1 = (const float4*)&d_Q[(size_t)cc1*128 + wn*32 + tig*4];
            const float4* P2 = (const float4*)&d_P[(size_t)r2*128 + wn*32 + tig*4];
            const float4* Q2 = (const float4*)&d_Q[(size_t)cc2*128 + wn*32 + tig*4];
            float4 a0 = P1[0], b0 = Q1[0], a1 = P1[4], b1 = Q1[4];
            float4 c0 = P2[0], d0 = Q2[0], c1 = P2[4], d1 = Q2[4];
            acc[0][0] = a0.x + b0.x; acc[0][1] = a0.y + b0.y;
            acc[1][0] = a0.z + b0.z; acc[1][1] = a0.w + b0.w;
            acc[0][2] = c0.x + d0.x; acc[0][3] = c0.y + d0.y;
            acc[1][2] = c0.z + d0.z; acc[1][3] = c0.w + d0.w;
            acc[2][0] = a1.x + b1.x; acc[2][1] = a1.y + b1.y;
            acc[3][0] = a1.z + b1.z; acc[3][1] = a1.w + b1.w;
            acc[2][2] = c1.x + d1.x; acc[2][3] = c1.y + d1.y;
            acc[3][2] = c1.z + d1.z; acc[3][3] = c1.w + d1.w;
        }
        #pragma unroll
        for (int s = 0; s < 2; s++) {
            uint32_t a[4];
            a[0] = sEA[e1*20 + s*8 + tig];
            a[1] = sEA[e2*20 + s*8 + tig];
            a[2] = sEA[e1*20 + s*8 + tig + 4];
            a[3] = sEA[e2*20 + s*8 + tig + 4];
            uint4 b01 = *(const uint4*)&sW1p[((wn*2 + s)*2 + 0)*128 + lane*4];
            uint4 b23 = *(const uint4*)&sW1p[((wn*2 + s)*2 + 1)*128 + lane*4];
            mma16(acc[0], a, b01.x, b01.y);
            mma16(acc[1], a, b01.z, b01.w);
            mma16(acc[2], a, b23.x, b23.y);
            mma16(acc[3], a, b23.z, b23.w);
        }
        #pragma unroll
        for (int nt = 0; nt < 4; nt++) {
            int cu = wn*16 + nt*4 + tig;
            sH[e1*68 + cu] = f2h2(fmaxf(acc[nt][0], 0.f), fmaxf(acc[nt][1], 0.f));
            sH[e2*68 + cu] = f2h2(fmaxf(acc[nt][2], 0.f), fmaxf(acc[nt][3], 0.f));
        }
        __syncthreads();

        // ======== GEMM2: EN = H1 @ W2 + b2 → outE + sEN ========
        float acc2[2][4];
        #pragma unroll
        for (int nt = 0; nt < 2; nt++) {
            int c = wn*16 + nt*8 + tig*2;
            acc2[nt][0] = sB2[c]; acc2[nt][1] = sB2[c+1];
            acc2[nt][2] = sB2[c]; acc2[nt][3] = sB2[c+1];
        }
        #pragma unroll
        for (int s = 0; s < 8; s++) {
            uint32_t a[4];
            a[0] = sH[e1*68 + s*8 + tig];
            a[1] = sH[e2*68 + s*8 + tig];
            a[2] = sH[e1*68 + s*8 + tig + 4];
            a[3] = sH[e2*68 + s*8 + tig + 4];
            uint4 b = *(const uint4*)&sW2p[(wn*8 + s)*128 + lane*4];
            mma16(acc2[0], a, b.x, b.y);
            mma16(acc2[1], a, b.z, b.w);
        }
        #pragma unroll
        for (int nt = 0; nt < 2; nt++) {
            int c = wn*16 + nt*8 + tig*2;
            *(float2*)&outE[(size_t)(e0 + e1)*64 + c] = make_float2(acc2[nt][0], acc2[nt][1]);
            *(float2*)&outE[(size_t)(e0 + e2)*64 + c] = make_float2(acc2[nt][2], acc2[nt][3]);
            int cu = wn*8 + nt*4 + tig;
            sEN[e1*36 + cu] = f2h2(acc2[nt][0], acc2[nt][1]);
            sEN[e2*36 + cu] = f2h2(acc2[nt][2], acc2[nt][3]);
        }
        __syncthreads();

        // ======== GEMM3: H2 = relu(Ms[row] + EN @ W3) ========
        {
            const float4* M1 = (const float4*)&d_Ms[(size_t)r1*128 + wn*32 + tig*4];
            const float4* M2 = (const float4*)&d_Ms[(size_t)r2*128 + wn*32 + tig*4];
            float4 a0 = M1[0], a1 = M1[4], b0 = M2[0], b1 = M2[4];
            acc[0][0] = a0.x; acc[0][1] = a0.y; acc[1][0] = a0.z; acc[1][1] = a0.w;
            acc[0][2] = b0.x; acc[0][3] = b0.y; acc[1][2] = b0.z; acc[1][3] = b0.w;
            acc[2][0] = a1.x; acc[2][1] = a1.y; acc[3][0] = a1.z; acc[3][1] = a1.w;
            acc[2][2] = b1.x; acc[2][3] = b1.y; acc[3][2] = b1.z; acc[3][3] = b1.w;
        }
        #pragma unroll
        for (int s = 0; s < 4; s++) {
            uint32_t a[4];
            a[0] = sEN[e1*36 + s*8 + tig];
            a[1] = sEN[e2*36 + s*8 + tig];
            a[2] = sEN[e1*36 + s*8 + tig + 4];
            a[3] = sEN[e2*36 + s*8 + tig + 4];
            uint4 b01 = *(const uint4*)&sW3p[((wn*4 + s)*2 + 0)*128 + lane*4];
            uint4 b23 = *(const uint4*)&sW3p[((wn*4 + s)*2 + 1)*128 + lane*4];
            mma16(acc[0], a, b01.x, b01.y);
            mma16(acc[1], a, b01.z, b01.w);
            mma16(acc[2], a, b23.x, b23.y);
            mma16(acc[3], a, b23.z, b23.w);
        }
        __syncthreads();   // GEMM2 reads of sH done before overwrite
        #pragma unroll
        for (int nt = 0; nt < 4; nt++) {
            int cu = wn*16 + nt*4 + tig;
            sH[e1*68 + cu] = f2h2(fmaxf(acc[nt][0], 0.f), fmaxf(acc[nt][1], 0.f));
            sH[e2*68 + cu] = f2h2(fmaxf(acc[nt][2], 0.f), fmaxf(acc[nt][3], 0.f));
        }
        __syncthreads();

        // ======== GEMM4: m = H2 @ W4 + b4 → TAU16 v4 scatter ========
        float acc4[4][4];
        #pragma unroll
        for (int nt = 0; nt < 4; nt++) {
            int c = wn*32 + nt*8 + tig*2;
            acc4[nt][0] = sB4[c]; acc4[nt][1] = sB4[c+1];
            acc4[nt][2] = sB4[c]; acc4[nt][3] = sB4[c+1];
        }
        #pragma unroll
        for (int s = 0; s < 8; s++) {
            uint32_t a[4];
            a[0] = sH[e1*68 + s*8 + tig];
            a[1] = sH[e2*68 + s*8 + tig];
            a[2] = sH[e1*68 + s*8 + tig + 4];
            a[3] = sH[e2*68 + s*8 + tig + 4];
            uint4 b01 = *(const uint4*)&sW4p[((wn*8 + s)*2 + 0)*128 + lane*4];
            uint4 b23 = *(const uint4*)&sW4p[((wn*8 + s)*2 + 1)*128 + lane*4];
            mma16(acc4[0], a, b01.x, b01.y);
            mma16(acc4[1], a, b01.z, b01.w);
            mma16(acc4[2], a, b23.x, b23.y);
            mma16(acc4[3], a, b23.z, b23.w);
        }
        {
            float* p1 = &d_agg[(size_t)cc1*128 + wn*32 + tig*4];
            red_add_v4f(p1,      acc4[0][0], acc4[0][1], acc4[1][0], acc4[1][1]);
            red_add_v4f(p1 + 16, acc4[2][0], acc4[2][1], acc4[3][0], acc4[3][1]);
            float* p2 = &d_agg[(size_t)cc2*128 + wn*32 + tig*4];
            red_add_v4f(p2,      acc4[0][2], acc4[0][3], acc4[1][2], acc4[1][3]);
            red_add_v4f(p2 + 16, acc4[2][2], acc4[2][3], acc4[3][2], acc4[3][3]);
        }
    }
}

// ---------------- K3: node MLP2 + pooling (fp32-exact; un-TAUs agg) ----------------
#define NODE_SMEM (49280 * 4)
__global__ void __launch_bounds__(512, 1)
k_node(const float* __restrict__ x, const float* __restrict__ u,
       const float* __restrict__ n2w1, const float* __restrict__ n2b1,
       const float* __restrict__ n2w2, const float* __restrict__ n2b2,
       const int* __restrict__ batch, float* __restrict__ outX) {
    extern __shared__ float sm[];
    float* sW1  = sm;
    float* sW2  = sm + 26624;
    float* sB1  = sm + 34816;
    float* sB2  = sm + 34944;
    float* sInT = sm + 35008;
    float* sInv = sm + 49152;
    int*   sBat = (int*)(sm + 49216);

    int tid = threadIdx.x, tx = tid & 31, wid = tid >> 5;
    int ty = wid & 7, fh = wid >> 3;
    int fbase = fh*64 + tx*2;
    int f2 = fh*32 + tx;

    for (int i = tid; i < 26624; i += 512) sW1[i] = n2w1[i];
    for (int i = tid; i < 8192;  i += 512) sW2[i] = n2w2[i];
    if (tid < 128) sB1[tid] = n2b1[tid];
    if (tid < 64)  sB2[tid] = n2b2[tid];

    int n0 = blockIdx.x * 64;
    if (tid < 64) {
        int n = n0 + tid;
        if (n < NN) { sBat[tid] = batch[n]; sInv[tid] = 1.f / fmaxf(d_deg[n], 1.f); }
        else        { sBat[tid] = 0;        sInv[tid] = 0.f; }
    }
    __syncthreads();
    for (int idx = tid; idx < 64*64; idx += 512) {
        int node = idx >> 6, k = idx & 63; int n = n0 + node;
        sInT[k*68 + node] = (n < NN) ? x[(size_t)n*64 + k] : 0.f;
    }
    for (int idx = tid; idx < 64*128; idx += 512) {
        int node = idx >> 7, k = idx & 127; int n = n0 + node;
        sInT[(64 + k)*68 + node] = (n < NN) ? d_agg[(size_t)n*128 + TAU16(k)] * sInv[node] : 0.f;
    }
    for (int idx = tid; idx < 64*16; idx += 512) {
        int node = idx >> 4, k = idx & 15;
        sInT[(192 + k)*68 + node] = u[sBat[node]*16 + k];
    }
    __syncthreads();

    ull acc[4][2];
    #pragma unroll
    for (int p = 0; p < 4; p++) {
        acc[p][0] = pack2(sB1[fbase],     sB1[fbase]);
        acc[p][1] = pack2(sB1[fbase + 1], sB1[fbase + 1]);
    }
    #pragma unroll 4
    for (int k = 0; k < 208; k++) {
        float2 B = *(const float2*)&sW1[k*128 + fbase];
        ull bb0 = pack2(B.x, B.x), bb1 = pack2(B.y, B.y);
        float4 A0 = *(const float4*)&sInT[k*68 + ty*8];
        float4 A1 = *(const float4*)&sInT[k*68 + ty*8 + 4];
        ull a0 = pack2(A0.x, A0.y), a1 = pack2(A0.z, A0.w);
        ull a2 = pack2(A1.x, A1.y), a3 = pack2(A1.z, A1.w);
        ffma2(acc[0][0], a0, bb0); ffma2(acc[0][1], a0, bb1);
        ffma2(acc[1][0], a1, bb0); ffma2(acc[1][1], a1, bb1);
        ffma2(acc[2][0], a2, bb0); ffma2(acc[2][1], a2, bb1);
        ffma2(acc[3][0], a3, bb0); ffma2(acc[3][1], a3, bb1);
    }
    __syncthreads();
    #pragma unroll
    for (int p = 0; p < 4; p++) {
        *(ull*)&sInT[(fbase + 0)*68 + ty*8 + 2*p] = relu2(acc[p][0]);
        *(ull*)&sInT[(fbase + 1)*68 + ty*8 + 2*p] = relu2(acc[p][1]);
    }
    __syncthreads();

    ull acc2[4];
    {
        float b = sB2[f2];
        #pragma unroll
        for (int p = 0; p < 4; p++) acc2[p] = pack2(b, b);
    }
    #pragma unroll 4
    for (int k = 0; k < 128; k++) {
        float bs = sW2[k*64 + f2];
        ull bb = pack2(bs, bs);
        float4 A0 = *(const float4*)&sInT[k*68 + ty*8];
        float4 A1 = *(const float4*)&sInT[k*68 + ty*8 + 4];
        ffma2(acc2[0], pack2(A0.x, A0.y), bb);
        ffma2(acc2[1], pack2(A0.z, A0.w), bb);
        ffma2(acc2[2], pack2(A1.x, A1.y), bb);
        ffma2(acc2[3], pack2(A1.z, A1.w), bb);
    }
    #pragma unroll
    for (int p = 0; p < 4; p++) {
        float2 v = unpack2(acc2[p]);
        int node = ty*8 + 2*p;
        int n_lo = n0 + node;
        if (n_lo < NN) {
            outX[(size_t)n_lo*64 + f2] = v.x;
            red_add_f(&d_gsum[sBat[node]*64 + f2], v.x);
        }
        if (n_lo + 1 < NN) {
            outX[(size_t)(n_lo+1)*64 + f2] = v.y;
            red_add_f(&d_gsum[sBat[node+1]*64 + f2], v.y);
        }
    }
}

// ---------------- K4: global MLP ----------------
__global__ void k_glob(const float* __restrict__ u,
                       const float* __restrict__ gw1, const float* __restrict__ gb1,
                       const float* __restrict__ gw2, const float* __restrict__ gb2,
                       float* __restrict__ outU) {
    __shared__ float sin[80];
    __shared__ float sh[128];
    int g = blockIdx.x, tid = threadIdx.x;
    if (tid < 16) sin[tid] = u[g*16 + tid];
    if (tid < 64) {
        float c = fmaxf(d_gcnt[g], 1.f);
        sin[16 + tid] = d_gsum[g*64 + tid] / c;
    }
    __syncthreads();
    float acc = gb1[tid];
    #pragma unroll 8
    for (int k = 0; k < 80; k++) acc += sin[k] * gw1[k*128 + tid];
    sh[tid] = fmaxf(acc, 0.f);
    __syncthreads();
    if (tid < 32) {
        float a2 = gb2[tid];
        #pragma unroll 8
        for (int k = 0; k < 128; k++) a2 += sh[k] * gw2[k*32 + tid];
        outU[g*32 + tid] = a2;
    }
}

// ---------------- launch ----------------
extern "C" void kernel_launch(void* const* d_in, const int* in_sizes, int n_in,
                              void* d_out, int out_size) {
    const float* x     = (const float*)d_in[0];
    const float* ea    = (const float*)d_in[1];
    const float* u     = (const float*)d_in[2];
    const float* ew1   = (const float*)d_in[3];
    const float* eb1   = (const float*)d_in[4];
    const float* ew2   = (const float*)d_in[5];
    const float* eb2   = (const float*)d_in[6];
    const float* n1w1  = (const float*)d_in[7];
    const float* n1b1  = (const float*)d_in[8];
    const float* n1w2  = (const float*)d_in[9];
    const float* n1b2  = (const float*)d_in[10];
    const float* n2w1  = (const float*)d_in[11];
    const float* n2b1  = (const float*)d_in[12];
    const float* n2w2  = (const float*)d_in[13];
    const float* n2b2  = (const float*)d_in[14];
    const float* gw1   = (const float*)d_in[15];
    const float* gb1   = (const float*)d_in[16];
    const float* gw2   = (const float*)d_in[17];
    const float* gb2   = (const float*)d_in[18];
    const int*   ei    = (const int*)d_in[19];
    const int*   batch = (const int*)d_in[20];

    float* out  = (float*)d_out;
    float* outX = out;
    float* outE = out + (size_t)NN*64;
    float* outU = out + (size_t)NN*64 + (size_t)NE*64;

    cudaFuncSetAttribute(k_pre,  cudaFuncAttributeMaxDynamicSharedMemorySize, PRE_SMEM);
    cudaFuncSetAttribute(k2,     cudaFuncAttributeMaxDynamicSharedMemorySize, S2_SMEM);
    cudaFuncSetAttribute(k_node, cudaFuncAttributeMaxDynamicSharedMemorySize, NODE_SMEM);

    k_zero<<<256, 256>>>();
    k_rg<<<(NG*128 + 255)/256, 256>>>(u, ew1);
    k_pre<<<(NN + 63)/64, 512, PRE_SMEM>>>(x, ew1, eb1, n1w1, n1b1, batch);
    k2<<<2*PGRID, 512, S2_SMEM>>>(ea, ew1, ew2, eb2, n1w1, n1w2, n1b2, ei, outE);
    k_count<<<(NE + 255)/256, 256>>>(ei, batch);
    k_node<<<(NN + 63)/64, 512, NODE_SMEM>>>(x, u, n2w1, n2b1, n2w2, n2b2, batch, outX);
    k_glob<<<NG, 128>>>(u, gw1, gb1, gw2, gb2, outU);
}

// round 14
// speedup vs baseline: 1.1190x; 1.1190x over previous
#include <cuda_runtime.h>
#include <cstdint>

#define NN 50000
#define NE 800000
#define NG 256
#define NTILE 6250          // NE / 128
#define PGRID 152

typedef unsigned long long ull;

// TAU16: within 16-blocks, col (8a+2t+b) -> pos (4t+2a+b)
__host__ __device__ __forceinline__ int TAU16(int c) {
    int j = c & 15;
    return (c & ~15) | (((j >> 1) & 3) << 2) | (((j >> 3) & 1) << 1) | (j & 1);
}

// ---------------- fp16 mma.sync helpers ----------------
__device__ __forceinline__ uint32_t f2h2(float lo, float hi) {
    uint32_t r; asm("cvt.rn.f16x2.f32 %0, %1, %2;" : "=r"(r) : "f"(hi), "f"(lo)); return r;
}
__device__ __forceinline__ void mma16(float* d, const uint32_t* a, uint32_t b0, uint32_t b1) {
    asm volatile("mma.sync.aligned.m16n8k16.row.col.f32.f16.f16.f32 "
        "{%0,%1,%2,%3},{%4,%5,%6,%7},{%8,%9},{%0,%1,%2,%3};"
        : "+f"(d[0]), "+f"(d[1]), "+f"(d[2]), "+f"(d[3])
        : "r"(a[0]), "r"(a[1]), "r"(a[2]), "r"(a[3]), "r"(b0), "r"(b1));
}
__device__ __forceinline__ void pf_l2(const void* p) {
    asm volatile("prefetch.global.L2 [%0];" :: "l"(p));
}

// ---------------- f32x2 helpers ----------------
__device__ __forceinline__ void ffma2(ull &d, ull a, ull b) {
    asm("fma.rn.f32x2 %0, %1, %2, %0;" : "+l"(d) : "l"(a), "l"(b));
}
__device__ __forceinline__ ull pack2(float lo, float hi) {
    ull r; asm("mov.b64 %0, {%1, %2};" : "=l"(r) : "f"(lo), "f"(hi)); return r;
}
__device__ __forceinline__ float2 unpack2(ull v) {
    float2 r; asm("mov.b64 {%0, %1}, %2;" : "=f"(r.x), "=f"(r.y) : "l"(v)); return r;
}
__device__ __forceinline__ ull relu2(ull v) {
    float2 t = unpack2(v);
    return pack2(fmaxf(t.x, 0.f), fmaxf(t.y, 0.f));
}
__device__ __forceinline__ void red_add_v4f(float* p, float a, float b, float c, float d) {
    asm volatile("red.global.add.v4.f32 [%0], {%1,%2,%3,%4};" :: "l"(p), "f"(a), "f"(b), "f"(c), "f"(d) : "memory");
}
__device__ __forceinline__ void red_add_f(float* p, float a) {
    asm volatile("red.global.add.f32 [%0], %1;" :: "l"(p), "f"(a) : "memory");
}

// ---------------- device scratch ----------------
__device__ float d_P [NN*128];   // (x@e_w1[:64] + Rg[batch] + eb1), TAU16 layout
__device__ float d_Q [NN*128];   // TAU16 layout
__device__ float d_Ms[NN*128];   // TAU16 layout
__device__ float d_Rg[NG*128];   // natural layout
__device__ float d_agg[NN*128];  // TAU16 layout
__device__ float d_deg[NN];
__device__ float d_gsum[NG*64];
__device__ float d_gcnt[NG];

// ---------------- K0 / K0b ----------------
__global__ void k_zero() {
    int i = blockIdx.x * blockDim.x + threadIdx.x;
    int stride = gridDim.x * blockDim.x;
    for (int idx = i; idx < NN*128; idx += stride) d_agg[idx] = 0.f;
    for (int idx = i; idx < NN;     idx += stride) d_deg[idx] = 0.f;
    for (int idx = i; idx < NG*64;  idx += stride) d_gsum[idx] = 0.f;
    for (int idx = i; idx < NG;     idx += stride) d_gcnt[idx] = 0.f;
}
__global__ void k_count(const int* __restrict__ ei, const int* __restrict__ batch) {
    int i = blockIdx.x * blockDim.x + threadIdx.x;
    if (i < NE) atomicAdd(&d_deg[ei[NE + i]], 1.f);
    if (i < NN) atomicAdd(&d_gcnt[batch[i]], 1.f);
}

// ---------------- K1b: R = u @ e_w1[160:176] ----------------
__global__ void k_rg(const float* __restrict__ u, const float* __restrict__ ew1) {
    int i = blockIdx.x * blockDim.x + threadIdx.x;
    if (i < NG*128) {
        int g = i >> 7, j = i & 127;
        float acc = 0.f;
        #pragma unroll
        for (int k = 0; k < 16; k++) acc += u[g*16 + k] * ew1[(160 + k)*128 + j];
        d_Rg[i] = acc;
    }
}

// ---------------- K1: precompute PR, Q, Msrc (fp32-exact; TAU16 store) ----------------
#define PRE_SMEM ((4352 + 3*8192 + 256 + 64) * 4)
__global__ void __launch_bounds__(512, 1)
k_pre(const float* __restrict__ x, const float* __restrict__ ew1,
      const float* __restrict__ eb1, const float* __restrict__ n1w1,
      const float* __restrict__ n1b1, const int* __restrict__ batch) {
    extern __shared__ float sm[];
    float* sXT  = sm;
    float* sWa  = sm + 4352;
    float* sWb  = sWa + 8192;
    float* sWm  = sWb + 8192;
    float* sEb1 = sWm + 8192;
    float* sNb1 = sEb1 + 128;
    int*   sBat = (int*)(sNb1 + 128);
    int tid = threadIdx.x;
    for (int i = tid; i < 8192; i += 512) {
        sWa[i] = ew1[i];
        sWb[i] = ew1[64*128 + i];
        sWm[i] = n1w1[i];
    }
    if (tid < 128) { sEb1[tid] = eb1[tid]; sNb1[tid] = n1b1[tid]; }
    int n0 = blockIdx.x * 64;
    if (tid < 64) {
        int n = n0 + tid;
        sBat[tid] = (n < NN) ? batch[n] : 0;
    }
    for (int idx = tid; idx < 64*64; idx += 512) {
        int node = idx >> 6, k = idx & 63;
        int n = n0 + node;
        sXT[k*68 + node] = (n < NN) ? x[(size_t)n*64 + k] : 0.f;
    }
    __syncthreads();
    int tx = tid & 31, wid = tid >> 5;
    int ty = wid & 7, fh = wid >> 3;
    int fbase = fh*64 + tx*2;
    int fdst = TAU16(fbase);
    for (int which = 0; which < 3; which++) {
        const float* W = (which == 0) ? sWa : (which == 1) ? sWb : sWm;
        ull acc[4][2];
        #pragma unroll
        for (int p = 0; p < 4; p++)
            #pragma unroll
            for (int j = 0; j < 2; j++) {
                float b = (which == 0) ? sEb1[fbase + j] : (which == 2) ? sNb1[fbase + j] : 0.f;
                acc[p][j] = pack2(b, b);
            }
        #pragma unroll 4
        for (int k = 0; k < 64; k++) {
            float2 B = *(const float2*)&W[k*128 + fbase];
            ull bb0 = pack2(B.x, B.x), bb1 = pack2(B.y, B.y);
            float4 A0 = *(const float4*)&sXT[k*68 + ty*8];
            float4 A1 = *(const float4*)&sXT[k*68 + ty*8 + 4];
            ull a0 = pack2(A0.x, A0.y), a1 = pack2(A0.z, A0.w);
            ull a2 = pack2(A1.x, A1.y), a3 = pack2(A1.z, A1.w);
            ffma2(acc[0][0], a0, bb0); ffma2(acc[0][1], a0, bb1);
            ffma2(acc[1][0], a1, bb0); ffma2(acc[1][1], a1, bb1);
            ffma2(acc[2][0], a2, bb0); ffma2(acc[2][1], a2, bb1);
            ffma2(acc[3][0], a3, bb0); ffma2(acc[3][1], a3, bb1);
        }
        float* dst = (which == 0) ? d_P : (which == 1) ? d_Q : d_Ms;
        #pragma unroll
        for (int p = 0; p < 4; p++) {
            float2 v0 = unpack2(acc[p][0]), v1 = unpack2(acc[p][1]);
            int node = ty*8 + 2*p;
            int n_lo = n0 + node;
            if (which == 0) {
                if (n_lo < NN) {
                    const float* rg = &d_Rg[(size_t)sBat[node]*128 + fbase];
                    v0.x += rg[0]; v1.x += rg[1];
                }
                if (n_lo + 1 < NN) {
                    const float* rg = &d_Rg[(size_t)sBat[node+1]*128 + fbase];
                    v0.y += rg[0]; v1.y += rg[1];
                }
            }
            if (n_lo < NN)
                *(float2*)&dst[(size_t)n_lo*128 + fdst] = make_float2(v0.x, v1.x);
            if (n_lo + 1 < NN)
                *(float2*)&dst[(size_t)(n_lo+1)*128 + fdst] = make_float2(v0.y, v1.y);
        }
    }
}

// ================= K2: merged edge pipeline (fp16 mma) — persistent, 1024 thr =================
// word layout:
//   sW1p 2048 | sW2p 4096 | sW3p 4096 | sW4p 8192 | sEA 2560 | sEN 4608 |
//   sH 8704 | sB2 64 | sB4 128 | idx 256   = 34752 words (139 KB)
#define S2_SMEM (34752 * 4)
__global__ void __launch_bounds__(1024, 1)
k2(const float* __restrict__ ea, const float* __restrict__ ew1,
   const float* __restrict__ ew2, const float* __restrict__ eb2,
   const float* __restrict__ n1w1, const float* __restrict__ n1w2,
   const float* __restrict__ n1b2,
   const int* __restrict__ ei, float* __restrict__ outE) {
    extern __shared__ float sm[];
    uint32_t* sW1p = (uint32_t*)sm;               // 2048
    uint32_t* sW2p = (uint32_t*)(sm + 2048);      // 4096
    uint32_t* sW3p = (uint32_t*)(sm + 6144);      // 4096
    uint32_t* sW4p = (uint32_t*)(sm + 10240);     // 8192
    uint32_t* sEA  = (uint32_t*)(sm + 18432);     // 2560  [e*20]
    uint32_t* sEN  = (uint32_t*)(sm + 20992);     // 4608  [e*36]
    uint32_t* sH   = (uint32_t*)(sm + 25600);     // 8704  [e*68]
    float*    sB2  = sm + 34304;                  // 64
    float*    sB4  = sm + 34368;                  // 128
    int* sRow = (int*)(sm + 34496);
    int* sCol = sRow + 128;

    int tid = threadIdx.x, lane = tid & 31, w = tid >> 5;
    int wm = w & 7, wn = w >> 3;
    int g = lane >> 2, tig = lane & 3;
    int e1 = wm*16 + g, e2 = e1 + 8;

    // ---- W1c^T fp16 staging (2048 words) ----
    for (int i = tid; i < 2048; i += 1024) {
        int q = i & 3, ln = (i >> 2) & 31, pr = (i >> 7) & 1;
        int s = (i >> 8) & 1, wn_ = (i >> 9) & 3;
        int gg = ln >> 2, tt = ln & 3;
        int nt = pr*2 + (q >> 1), hb = q & 1;
        int n = (wn_*4 + nt)*8 + gg;
        int k0 = s*16 + 2*tt + hb*8;
        sW1p[i] = f2h2(ew1[(128 + k0)*128 + n], ew1[(128 + k0 + 1)*128 + n]);
    }
    // ---- W2^T fp16 staging (4096 words) ----
    for (int i = tid; i < 4096; i += 1024) {
        int q = i & 3, ln = (i >> 2) & 31;
        int s = (i >> 7) & 7, wn_ = (i >> 10) & 3;
        int gg = ln >> 2, tt = ln & 3;
        int nt = q >> 1, hb = q & 1;
        int n = (wn_*2 + nt)*8 + gg;
        int k0 = s*16 + 2*tt + hb*8;
        sW2p[i] = f2h2(ew2[k0*64 + n], ew2[(k0 + 1)*64 + n]);
    }
    // ---- W3^T fp16 staging (4096 words) ----
    for (int i = tid; i < 4096; i += 1024) {
        int q = i & 3, ln = (i >> 2) & 31, pr = (i >> 7) & 1;
        int s = (i >> 8) & 3, wn_ = (i >> 10) & 3;
        int gg = ln >> 2, tt = ln & 3;
        int nt = pr*2 + (q >> 1), hb = q & 1;
        int n = (wn_*4 + nt)*8 + gg;
        int k0 = s*16 + 2*tt + hb*8;
        sW3p[i] = f2h2(n1w1[(64 + k0)*128 + n], n1w1[(64 + k0 + 1)*128 + n]);
    }
    // ---- W4^T fp16 staging (8192 words) ----
    for (int i = tid; i < 8192; i += 1024) {
        int q = i & 3, ln = (i >> 2) & 31, pr = (i >> 7) & 1;
        int s = (i >> 8) & 7, wn_ = (i >> 11) & 3;
        int gg = ln >> 2, tt = ln & 3;
        int nt = pr*2 + (q >> 1), hb = q & 1;
        int n = (wn_*4 + nt)*8 + gg;
        int k0 = s*16 + 2*tt + hb*8;
        sW4p[i] = f2h2(n1w2[k0*128 + n], n1w2[(k0 + 1)*128 + n]);
    }
    if (tid < 64)  sB2[tid] = eb2[tid];
    if (tid < 128) sB4[tid] = n1b2[tid];

    for (int t = blockIdx.x; t < NTILE; t += gridDim.x) {
        __syncthreads();     // previous-tile sH/sEN reads done
        int e0 = t * 128;
        if (tid < 128) {
            sRow[tid] = ei[e0 + tid];
            sCol[tid] = ei[NE + e0 + tid];
        }
        if (tid < 512) {     // stage EA [128][32] fp16 (coalesced)
            int e = tid >> 2, ch = tid & 3;
            float4 v0 = *(const float4*)&ea[(size_t)(e0 + e)*32 + ch*8];
            float4 v1 = *(const float4*)&ea[(size_t)(e0 + e)*32 + ch*8 + 4];
            *(uint4*)&sEA[e*20 + ch*4] = make_uint4(
                f2h2(v0.x, v0.y), f2h2(v0.z, v0.w), f2h2(v1.x, v1.y), f2h2(v1.z, v1.w));
        }
        // ---- next-tile L2 prefetch: seeds + EA (issue-only, no registers held) ----
        {
            int tn = t + gridDim.x;
            if (tn < NTILE && tid >= 512) {
                int i = tid - 512;               // 0..511
                int e = i >> 2, sec = (i & 3) << 5;   // edge 0..127, sector 0/32/64/96
                int en = tn*128 + e;
                int rn = ei[en], cn = ei[NE + en];
                pf_l2(&d_P [(size_t)rn*128 + sec]);
                pf_l2(&d_Q [(size_t)cn*128 + sec]);
                pf_l2(&d_Ms[(size_t)rn*128 + sec]);
                if ((i & 3) == 0) pf_l2(&ea[(size_t)en*32]);
            }
        }
        __syncthreads();

        int r1 = sRow[e1], cc1 = sCol[e1];
        int r2 = sRow[e2], cc2 = sCol[e2];

        // ======== GEMM1: H1 = relu(PR[row] + Q[col] + EA @ W1c) ========
        float acc[4][4];
        {
            const float4* P1 = (const float4*)&d_P[(size_t)r1*128 + wn*32 + tig*4];
            const float4* Q1 = (const float4*)&d_Q[(size_t)cc1*128 + wn*32 + tig*4];
            const float4* P2 = (const float4*)&d_P[(size_t)r2*128 + wn*32 + tig*4];
            const float4* Q2 = (const float4*)&d_Q[(size_t)cc2*128 + wn*32 + tig*4];
            float4 a0 = P1[0], b0 = Q1[0], a1 = P1[4], b1 = Q1[4];
            float4 c0 = P2[0], d0 = Q2[0], c1 = P2[4], d1 = Q2[4];
            acc[0][0] = a0.x + b0.x; acc[0][1] = a0.y + b0.y;
            acc[1][0] = a0.z + b0.z; acc[1][1] = a0.w + b0.w;
            acc[0][2] = c0.x + d0.x; acc[0][3] = c0.y + d0.y;
            acc[1][2] = c0.z + d0.z; acc[1][3] = c0.w + d0.w;
            acc[2][0] = a1.x + b1.x; acc[2][1] = a1.y + b1.y;
            acc[3][0] = a1.z + b1.z; acc[3][1] = a1.w + b1.w;
            acc[2][2] = c1.x + d1.x; acc[2][3] = c1.y + d1.y;
            acc[3][2] = c1.z + d1.z; acc[3][3] = c1.w + d1.w;
        }
        #pragma unroll
        for (int s = 0; s < 2; s++) {
            uint32_t a[4];
            a[0] = sEA[e1*20 + s*8 + tig];
            a[1] = sEA[e2*20 + s*8 + tig];
            a[2] = sEA[e1*20 + s*8 + tig + 4];
            a[3] = sEA[e2*20 + s*8 + tig + 4];
            uint4 b01 = *(const uint4*)&sW1p[((wn*2 + s)*2 + 0)*128 + lane*4];
            uint4 b23 = *(const uint4*)&sW1p[((wn*2 + s)*2 + 1)*128 + lane*4];
            mma16(acc[0], a, b01.x, b01.y);
            mma16(acc[1], a, b01.z, b01.w);
            mma16(acc[2], a, b23.x, b23.y);
            mma16(acc[3], a, b23.z, b23.w);
        }
        #pragma unroll
        for (int nt = 0; nt < 4; nt++) {
            int cu = wn*16 + nt*4 + tig;
            sH[e1*68 + cu] = f2h2(fmaxf(acc[nt][0], 0.f), fmaxf(acc[nt][1], 0.f));
            sH[e2*68 + cu] = f2h2(fmaxf(acc[nt][2], 0.f), fmaxf(acc[nt][3], 0.f));
        }
        __syncthreads();

        // ======== GEMM2: EN = H1 @ W2 + b2 → outE + sEN ========
        float acc2[2][4];
        #pragma unroll
        for (int nt = 0; nt < 2; nt++) {
            int c = wn*16 + nt*8 + tig*2;
            acc2[nt][0] = sB2[c]; acc2[nt][1] = sB2[c+1];
            acc2[nt][2] = sB2[c]; acc2[nt][3] = sB2[c+1];
        }
        #pragma unroll
        for (int s = 0; s < 8; s++) {
            uint32_t a[4];
            a[0] = sH[e1*68 + s*8 + tig];
            a[1] = sH[e2*68 + s*8 + tig];
            a[2] = sH[e1*68 + s*8 + tig + 4];
            a[3] = sH[e2*68 + s*8 + tig + 4];
            uint4 b = *(const uint4*)&sW2p[(wn*8 + s)*128 + lane*4];
            mma16(acc2[0], a, b.x, b.y);
            mma16(acc2[1], a, b.z, b.w);
        }
        #pragma unroll
        for (int nt = 0; nt < 2; nt++) {
            int c = wn*16 + nt*8 + tig*2;
            *(float2*)&outE[(size_t)(e0 + e1)*64 + c] = make_float2(acc2[nt][0], acc2[nt][1]);
            *(float2*)&outE[(size_t)(e0 + e2)*64 + c] = make_float2(acc2[nt][2], acc2[nt][3]);
            int cu = wn*8 + nt*4 + tig;
            sEN[e1*36 + cu] = f2h2(acc2[nt][0], acc2[nt][1]);
            sEN[e2*36 + cu] = f2h2(acc2[nt][2], acc2[nt][3]);
        }
        __syncthreads();

        // ======== GEMM3: H2 = relu(Ms[row] + EN @ W3) ========
        {
            const float4* M1 = (const float4*)&d_Ms[(size_t)r1*128 + wn*32 + tig*4];
            const float4* M2 = (const float4*)&d_Ms[(size_t)r2*128 + wn*32 + tig*4];
            float4 a0 = M1[0], a1 = M1[4], b0 = M2[0], b1 = M2[4];
            acc[0][0] = a0.x; acc[0][1] = a0.y; acc[1][0] = a0.z; acc[1][1] = a0.w;
            acc[0][2] = b0.x; acc[0][3] = b0.y; acc[1][2] = b0.z; acc[1][3] = b0.w;
            acc[2][0] = a1.x; acc[2][1] = a1.y; acc[3][0] = a1.z; acc[3][1] = a1.w;
            acc[2][2] = b1.x; acc[2][3] = b1.y; acc[3][2] = b1.z; acc[3][3] = b1.w;
        }
        #pragma unroll
        for (int s = 0; s < 4; s++) {
            uint32_t a[4];
            a[0] = sEN[e1*36 + s*8 + tig];
            a[1] = sEN[e2*36 + s*8 + tig];
            a[2] = sEN[e1*36 + s*8 + tig + 4];
            a[3] = sEN[e2*36 + s*8 + tig + 4];
            uint4 b01 = *(const uint4*)&sW3p[((wn*4 + s)*2 + 0)*128 + lane*4];
            uint4 b23 = *(const uint4*)&sW3p[((wn*4 + s)*2 + 1)*128 + lane*4];
            mma16(acc[0], a, b01.x, b01.y);
            mma16(acc[1], a, b01.z, b01.w);
            mma16(acc[2], a, b23.x, b23.y);
            mma16(acc[3], a, b23.z, b23.w);
        }
        __syncthreads();   // GEMM2 reads of sH done before overwrite
        #pragma unroll
        for (int nt = 0; nt < 4; nt++) {
            int cu = wn*16 + nt*4 + tig;
            sH[e1*68 + cu] = f2h2(fmaxf(acc[nt][0], 0.f), fmaxf(acc[nt][1], 0.f));
            sH[e2*68 + cu] = f2h2(fmaxf(acc[nt][2], 0.f), fmaxf(acc[nt][3], 0.f));
        }
        __syncthreads();

        // ======== GEMM4: m = H2 @ W4 + b4 → TAU16 v4 scatter ========
        float acc4[4][4];
        #pragma unroll
        for (int nt = 0; nt < 4; nt++) {
            int c = wn*32 + nt*8 + tig*2;
            acc4[nt][0] = sB4[c]; acc4[nt][1] = sB4[c+1];
            acc4[nt][2] = sB4[c]; acc4[nt][3] = sB4[c+1];
        }
        #pragma unroll
        for (int s = 0; s < 8; s++) {
            uint32_t a[4];
            a[0] = sH[e1*68 + s*8 + tig];
            a[1] = sH[e2*68 + s*8 + tig];
            a[2] = sH[e1*68 + s*8 + tig + 4];
            a[3] = sH[e2*68 + s*8 + tig + 4];
            uint4 b01 = *(const uint4*)&sW4p[((wn*8 + s)*2 + 0)*128 + lane*4];
            uint4 b23 = *(const uint4*)&sW4p[((wn*8 + s)*2 + 1)*128 + lane*4];
            mma16(acc4[0], a, b01.x, b01.y);
            mma16(acc4[1], a, b01.z, b01.w);
            mma16(acc4[2], a, b23.x, b23.y);
            mma16(acc4[3], a, b23.z, b23.w);
        }
        {
            float* p1 = &d_agg[(size_t)cc1*128 + wn*32 + tig*4];
            red_add_v4f(p1,      acc4[0][0], acc4[0][1], acc4[1][0], acc4[1][1]);
            red_add_v4f(p1 + 16, acc4[2][0], acc4[2][1], acc4[3][0], acc4[3][1]);
            float* p2 = &d_agg[(size_t)cc2*128 + wn*32 + tig*4];
            red_add_v4f(p2,      acc4[0][2], acc4[0][3], acc4[1][2], acc4[1][3]);
            red_add_v4f(p2 + 16, acc4[2][2], acc4[2][3], acc4[3][2], acc4[3][3]);
        }
    }
}

// ---------------- K3: node MLP2 + pooling (fp32-exact; un-TAUs agg) ----------------
#define NODE_SMEM (49280 * 4)
__global__ void __launch_bounds__(512, 1)
k_node(const float* __restrict__ x, const float* __restrict__ u,
       const float* __restrict__ n2w1, const float* __restrict__ n2b1,
       const float* __restrict__ n2w2, const float* __restrict__ n2b2,
       const int* __restrict__ batch, float* __restrict__ outX) {
    extern __shared__ float sm[];
    float* sW1  = sm;
    float* sW2  = sm + 26624;
    float* sB1  = sm + 34816;
    float* sB2  = sm + 34944;
    float* sInT = sm + 35008;
    float* sInv = sm + 49152;
    int*   sBat = (int*)(sm + 49216);

    int tid = threadIdx.x, tx = tid & 31, wid = tid >> 5;
    int ty = wid & 7, fh = wid >> 3;
    int fbase = fh*64 + tx*2;
    int f2 = fh*32 + tx;

    for (int i = tid; i < 26624; i += 512) sW1[i] = n2w1[i];
    for (int i = tid; i < 8192;  i += 512) sW2[i] = n2w2[i];
    if (tid < 128) sB1[tid] = n2b1[tid];
    if (tid < 64)  sB2[tid] = n2b2[tid];

    int n0 = blockIdx.x * 64;
    if (tid < 64) {
        int n = n0 + tid;
        if (n < NN) { sBat[tid] = batch[n]; sInv[tid] = 1.f / fmaxf(d_deg[n], 1.f); }
        else        { sBat[tid] = 0;        sInv[tid] = 0.f; }
    }
    __syncthreads();
    for (int idx = tid; idx < 64*64; idx += 512) {
        int node = idx >> 6, k = idx & 63; int n = n0 + node;
        sInT[k*68 + node] = (n < NN) ? x[(size_t)n*64 + k] : 0.f;
    }
    for (int idx = tid; idx < 64*128; idx += 512) {
        int node = idx >> 7, k = idx & 127; int n = n0 + node;
        sInT[(64 + k)*68 + node] = (n < NN) ? d_agg[(size_t)n*128 + TAU16(k)] * sInv[node] : 0.f;
    }
    for (int idx = tid; idx < 64*16; idx += 512) {
        int node = idx >> 4, k = idx & 15;
        sInT[(192 + k)*68 + node] = u[sBat[node]*16 + k];
    }
    __syncthreads();

    ull acc[4][2];
    #pragma unroll
    for (int p = 0; p < 4; p++) {
        acc[p][0] = pack2(sB1[fbase],     sB1[fbase]);
        acc[p][1] = pack2(sB1[fbase + 1], sB1[fbase + 1]);
    }
    #pragma unroll 4
    for (int k = 0; k < 208; k++) {
        float2 B = *(const float2*)&sW1[k*128 + fbase];
        ull bb0 = pack2(B.x, B.x), bb1 = pack2(B.y, B.y);
        float4 A0 = *(const float4*)&sInT[k*68 + ty*8];
        float4 A1 = *(const float4*)&sInT[k*68 + ty*8 + 4];
        ull a0 = pack2(A0.x, A0.y), a1 = pack2(A0.z, A0.w);
        ull a2 = pack2(A1.x, A1.y), a3 = pack2(A1.z, A1.w);
        ffma2(acc[0][0], a0, bb0); ffma2(acc[0][1], a0, bb1);
        ffma2(acc[1][0], a1, bb0); ffma2(acc[1][1], a1, bb1);
        ffma2(acc[2][0], a2, bb0); ffma2(acc[2][1], a2, bb1);
        ffma2(acc[3][0], a3, bb0); ffma2(acc[3][1], a3, bb1);
    }
    __syncthreads();
    #pragma unroll
    for (int p = 0; p < 4; p++) {
        *(ull*)&sInT[(fbase + 0)*68 + ty*8 + 2*p] = relu2(acc[p][0]);
        *(ull*)&sInT[(fbase + 1)*68 + ty*8 + 2*p] = relu2(acc[p][1]);
    }
    __syncthreads();

    ull acc2[4];
    {
        float b = sB2[f2];
        #pragma unroll
        for (int p = 0; p < 4; p++) acc2[p] = pack2(b, b);
    }
    #pragma unroll 4
    for (int k = 0; k < 128; k++) {
        float bs = sW2[k*64 + f2];
        ull bb = pack2(bs, bs);
        float4 A0 = *(const float4*)&sInT[k*68 + ty*8];
        float4 A1 = *(const float4*)&sInT[k*68 + ty*8 + 4];
        ffma2(acc2[0], pack2(A0.x, A0.y), bb);
        ffma2(acc2[1], pack2(A0.z, A0.w), bb);
        ffma2(acc2[2], pack2(A1.x, A1.y), bb);
        ffma2(acc2[3], pack2(A1.z, A1.w), bb);
    }
    #pragma unroll
    for (int p = 0; p < 4; p++) {
        float2 v = unpack2(acc2[p]);
        int node = ty*8 + 2*p;
        int n_lo = n0 + node;
        if (n_lo < NN) {
            outX[(size_t)n_lo*64 + f2] = v.x;
            red_add_f(&d_gsum[sBat[node]*64 + f2], v.x);
        }
        if (n_lo + 1 < NN) {
            outX[(size_t)(n_lo+1)*64 + f2] = v.y;
            red_add_f(&d_gsum[sBat[node+1]*64 + f2], v.y);
        }
    }
}

// ---------------- K4: global MLP ----------------
__global__ void k_glob(const float* __restrict__ u,
                       const float* __restrict__ gw1, const float* __restrict__ gb1,
                       const float* __restrict__ gw2, const float* __restrict__ gb2,
                       float* __restrict__ outU) {
    __shared__ float sin[80];
    __shared__ float sh[128];
    int g = blockIdx.x, tid = threadIdx.x;
    if (tid < 16) sin[tid] = u[g*16 + tid];
    if (tid < 64) {
        float c = fmaxf(d_gcnt[g], 1.f);
        sin[16 + tid] = d_gsum[g*64 + tid] / c;
    }
    __syncthreads();
    float acc = gb1[tid];
    #pragma unroll 8
    for (int k = 0; k < 80; k++) acc += sin[k] * gw1[k*128 + tid];
    sh[tid] = fmaxf(acc, 0.f);
    __syncthreads();
    if (tid < 32) {
        float a2 = gb2[tid];
        #pragma unroll 8
        for (int k = 0; k < 128; k++) a2 += sh[k] * gw2[k*32 + tid];
        outU[g*32 + tid] = a2;
    }
}

// ---------------- launch ----------------
extern "C" void kernel_launch(void* const* d_in, const int* in_sizes, int n_in,
                              void* d_out, int out_size) {
    const float* x     = (const float*)d_in[0];
    const float* ea    = (const float*)d_in[1];
    const float* u     = (const float*)d_in[2];
    const float* ew1   = (const float*)d_in[3];
    const float* eb1   = (const float*)d_in[4];
    const float* ew2   = (const float*)d_in[5];
    const float* eb2   = (const float*)d_in[6];
    const float* n1w1  = (const float*)d_in[7];
    const float* n1b1  = (const float*)d_in[8];
    const float* n1w2  = (const float*)d_in[9];
    const float* n1b2  = (const float*)d_in[10];
    const float* n2w1  = (const float*)d_in[11];
    const float* n2b1  = (const float*)d_in[12];
    const float* n2w2  = (const float*)d_in[13];
    const float* n2b2  = (const float*)d_in[14];
    const float* gw1   = (const float*)d_in[15];
    const float* gb1   = (const float*)d_in[16];
    const float* gw2   = (const float*)d_in[17];
    const float* gb2   = (const float*)d_in[18];
    const int*   ei    = (const int*)d_in[19];
    const int*   batch = (const int*)d_in[20];

    float* out  = (float*)d_out;
    float* outX = out;
    float* outE = out + (size_t)NN*64;
    float* outU = out + (size_t)NN*64 + (size_t)NE*64;

    cudaFuncSetAttribute(k_pre,  cudaFuncAttributeMaxDynamicSharedMemorySize, PRE_SMEM);
    cudaFuncSetAttribute(k2,     cudaFuncAttributeMaxDynamicSharedMemorySize, S2_SMEM);
    cudaFuncSetAttribute(k_node, cudaFuncAttributeMaxDynamicSharedMemorySize, NODE_SMEM);

    k_zero<<<256, 256>>>();
    k_rg<<<(NG*128 + 255)/256, 256>>>(u, ew1);
    k_pre<<<(NN + 63)/64, 512, PRE_SMEM>>>(x, ew1, eb1, n1w1, n1b1, batch);
    k2<<<PGRID, 1024, S2_SMEM>>>(ea, ew1, ew2, eb2, n1w1, n1w2, n1b2, ei, outE);
    k_count<<<(NE + 255)/256, 256>>>(ei, batch);
    k_node<<<(NN + 63)/64, 512, NODE_SMEM>>>(x, u, n2w1, n2b1, n2w2, n2b2, batch, outX);
    k_glob<<<NG, 128>>>(u, gw1, gb1, gw2, gb2, outU);
}

// round 15
// speedup vs baseline: 1.3295x; 1.1881x over previous
#include <cuda_runtime.h>
#include <cstdint>

#define NN 50000
#define NE 800000
#define NG 256
#define NTILE 6250          // NE / 128
#define PGRID 152

typedef unsigned long long ull;

// TAU16: within 16-blocks, col (8a+2t+b) -> pos (4t+2a+b)
__host__ __device__ __forceinline__ int TAU16(int c) {
    int j = c & 15;
    return (c & ~15) | (((j >> 1) & 3) << 2) | (((j >> 3) & 1) << 1) | (j & 1);
}

// ---------------- fp16 mma.sync helpers ----------------
__device__ __forceinline__ uint32_t f2h2(float lo, float hi) {
    uint32_t r; asm("cvt.rn.f16x2.f32 %0, %1, %2;" : "=r"(r) : "f"(hi), "f"(lo)); return r;
}
__device__ __forceinline__ void mma16(float* d, const uint32_t* a, uint32_t b0, uint32_t b1) {
    asm volatile("mma.sync.aligned.m16n8k16.row.col.f32.f16.f16.f32 "
        "{%0,%1,%2,%3},{%4,%5,%6,%7},{%8,%9},{%0,%1,%2,%3};"
        : "+f"(d[0]), "+f"(d[1]), "+f"(d[2]), "+f"(d[3])
        : "r"(a[0]), "r"(a[1]), "r"(a[2]), "r"(a[3]), "r"(b0), "r"(b1));
}
__device__ __forceinline__ void red_add_v4f(float* p, float a, float b, float c, float d) {
    asm volatile("red.global.add.v4.f32 [%0], {%1,%2,%3,%4};" :: "l"(p), "f"(a), "f"(b), "f"(c), "f"(d) : "memory");
}
__device__ __forceinline__ void red_add_f(float* p, float a) {
    asm volatile("red.global.add.f32 [%0], %1;" :: "l"(p), "f"(a) : "memory");
}

// ---------------- device scratch ----------------
__device__ float d_P [NN*128];   // (x@e_w1[:64] + Rg[batch] + eb1), TAU16 layout
__device__ float d_Q [NN*128];   // TAU16 layout
__device__ float d_Ms[NN*128];   // TAU16 layout
__device__ float d_Rg[NG*128];   // TAU16 layout, eb1 folded in
__device__ float d_agg[NN*128];  // TAU16 layout
__device__ float d_deg[NN];
__device__ float d_gsum[NG*64];
__device__ float d_gcnt[NG];

// ---------------- K0 / K0b ----------------
__global__ void k_zero() {
    int i = blockIdx.x * blockDim.x + threadIdx.x;
    int stride = gridDim.x * blockDim.x;
    for (int idx = i; idx < NN*128; idx += stride) d_agg[idx] = 0.f;
    for (int idx = i; idx < NN;     idx += stride) d_deg[idx] = 0.f;
    for (int idx = i; idx < NG*64;  idx += stride) d_gsum[idx] = 0.f;
    for (int idx = i; idx < NG;     idx += stride) d_gcnt[idx] = 0.f;
}
__global__ void k_count(const int* __restrict__ ei, const int* __restrict__ batch) {
    int i = blockIdx.x * blockDim.x + threadIdx.x;
    if (i < NE) atomicAdd(&d_deg[ei[NE + i]], 1.f);
    if (i < NN) atomicAdd(&d_gcnt[batch[i]], 1.f);
}

// ---------------- K1b: Rg_tau = TAU16(u @ e_w1[160:176] + eb1) ----------------
__global__ void k_rg(const float* __restrict__ u, const float* __restrict__ ew1,
                     const float* __restrict__ eb1) {
    int i = blockIdx.x * blockDim.x + threadIdx.x;
    if (i < NG*128) {
        int g = i >> 7, j = i & 127;
        float acc = eb1[j];
        #pragma unroll
        for (int k = 0; k < 16; k++) acc += u[g*16 + k] * ew1[(160 + k)*128 + j];
        d_Rg[g*128 + TAU16(j)] = acc;
    }
}

// ---------------- K1: precompute P, Q, Ms via fp16 mma (TAU16 store) ----------------
// words: sWa 4096 | sWb 4096 | sWm 4096 | sX 2304 [n*36] | sBmt 128 | sBat 64 = 14784
#define PRE_SMEM (14784 * 4)
__global__ void __launch_bounds__(512, 1)
k_pre(const float* __restrict__ x, const float* __restrict__ ew1,
      const float* __restrict__ n1w1, const float* __restrict__ n1b1,
      const int* __restrict__ batch) {
    extern __shared__ float sm[];
    uint32_t* sWa  = (uint32_t*)sm;               // 4096
    uint32_t* sWb  = (uint32_t*)(sm + 4096);      // 4096
    uint32_t* sWm  = (uint32_t*)(sm + 8192);      // 4096
    uint32_t* sX   = (uint32_t*)(sm + 12288);     // 2304 [n*36]
    float*    sBmt = sm + 14592;                  // 128 (n1b1, TAU16-permuted)
    int*      sBat = (int*)(sm + 14720);          // 64

    int tid = threadIdx.x, lane = tid & 31, w = tid >> 5;
    int wm = w & 3, wn = w >> 2;
    int g = lane >> 2, tig = lane & 3;
    int e1 = wm*16 + g, e2 = e1 + 8;

    // ---- weight fragment staging (K=64 → 4 s-steps, N=128) ----
    for (int i = tid; i < 4096; i += 512) {
        int q = i & 3, ln = (i >> 2) & 31, pr = (i >> 7) & 1;
        int s = (i >> 8) & 3, wn_ = (i >> 10) & 3;
        int gg = ln >> 2, tt = ln & 3;
        int nt = pr*2 + (q >> 1), hb = q & 1;
        int n = (wn_*4 + nt)*8 + gg;
        int k0 = s*16 + 2*tt + hb*8;
        sWa[i] = f2h2(ew1[k0*128 + n],        ew1[(k0 + 1)*128 + n]);
        sWb[i] = f2h2(ew1[(64 + k0)*128 + n], ew1[(64 + k0 + 1)*128 + n]);
        sWm[i] = f2h2(n1w1[k0*128 + n],       n1w1[(k0 + 1)*128 + n]);
    }
    if (tid < 128) sBmt[TAU16(tid)] = n1b1[tid];

    int n0 = blockIdx.x * 64;
    if (tid < 64) {
        int n = n0 + tid;
        sBat[tid] = (n < NN) ? batch[n] : 0;
    }
    // ---- stage x [64][64] fp16, stride 36 u32 ----
    for (int i = tid; i < 64*32; i += 512) {
        int row = i >> 5, c2 = i & 31;
        int n = n0 + row;
        float a = 0.f, b = 0.f;
        if (n < NN) { a = x[(size_t)n*64 + 2*c2]; b = x[(size_t)n*64 + 2*c2 + 1]; }
        sX[row*36 + c2] = f2h2(a, b);
    }
    __syncthreads();

    for (int which = 0; which < 3; which++) {
        const uint32_t* W = (which == 0) ? sWa : (which == 1) ? sWb : sWm;
        float acc[4][4];
        #pragma unroll
        for (int nt = 0; nt < 4; nt++)
            #pragma unroll
            for (int j = 0; j < 4; j++) acc[nt][j] = 0.f;
        #pragma unroll
        for (int s = 0; s < 4; s++) {
            uint32_t a[4];
            a[0] = sX[e1*36 + s*8 + tig];
            a[1] = sX[e2*36 + s*8 + tig];
            a[2] = sX[e1*36 + s*8 + tig + 4];
            a[3] = sX[e2*36 + s*8 + tig + 4];
            uint4 b01 = *(const uint4*)&W[((wn*4 + s)*2 + 0)*128 + lane*4];
            uint4 b23 = *(const uint4*)&W[((wn*4 + s)*2 + 1)*128 + lane*4];
            mma16(acc[0], a, b01.x, b01.y);
            mma16(acc[1], a, b01.z, b01.w);
            mma16(acc[2], a, b23.x, b23.y);
            mma16(acc[3], a, b23.z, b23.w);
        }
        float* dst = (which == 0) ? d_P : (which == 1) ? d_Q : d_Ms;
        int pos = wn*32 + tig*4;
        #pragma unroll
        for (int half = 0; half < 2; half++) {      // half 0 = e1, 1 = e2
            int e = half ? e2 : e1;
            int n = n0 + e;
            if (n >= NN) continue;
            int o = half ? 2 : 0;
            float4 v0 = make_float4(acc[0][o], acc[0][o+1], acc[1][o], acc[1][o+1]);
            float4 v1 = make_float4(acc[2][o], acc[2][o+1], acc[3][o], acc[3][o+1]);
            if (which == 0) {   // += Rg_tau[batch] (eb1 folded)
                const float4* rg = (const float4*)&d_Rg[(size_t)sBat[e]*128 + pos];
                float4 r0 = rg[0], r1 = rg[4];
                v0.x += r0.x; v0.y += r0.y; v0.z += r0.z; v0.w += r0.w;
                v1.x += r1.x; v1.y += r1.y; v1.z += r1.z; v1.w += r1.w;
            } else if (which == 2) {   // += n1b1 (TAU16-staged)
                const float4* bm = (const float4*)&sBmt[pos];
                float4 r0 = bm[0], r1 = bm[4];
                v0.x += r0.x; v0.y += r0.y; v0.z += r0.z; v0.w += r0.w;
                v1.x += r1.x; v1.y += r1.y; v1.z += r1.z; v1.w += r1.w;
            }
            *(float4*)&dst[(size_t)n*128 + pos]      = v0;
            *(float4*)&dst[(size_t)n*128 + pos + 16] = v1;
        }
    }
}

// ================= K2: merged edge pipeline (fp16 mma) — persistent, 1024 thr =================
#define S2_SMEM (34752 * 4)
__global__ void __launch_bounds__(1024, 1)
k2(const float* __restrict__ ea, const float* __restrict__ ew1,
   const float* __restrict__ ew2, const float* __restrict__ eb2,
   const float* __restrict__ n1w1, const float* __restrict__ n1w2,
   const float* __restrict__ n1b2,
   const int* __restrict__ ei, float* __restrict__ outE) {
    extern __shared__ float sm[];
    uint32_t* sW1p = (uint32_t*)sm;               // 2048
    uint32_t* sW2p = (uint32_t*)(sm + 2048);      // 4096
    uint32_t* sW3p = (uint32_t*)(sm + 6144);      // 4096
    uint32_t* sW4p = (uint32_t*)(sm + 10240);     // 8192
    uint32_t* sEA  = (uint32_t*)(sm + 18432);     // 2560  [e*20]
    uint32_t* sEN  = (uint32_t*)(sm + 20992);     // 4608  [e*36]
    uint32_t* sH   = (uint32_t*)(sm + 25600);     // 8704  [e*68]
    float*    sB2  = sm + 34304;
    float*    sB4  = sm + 34368;
    int* sRow = (int*)(sm + 34496);
    int* sCol = sRow + 128;

    int tid = threadIdx.x, lane = tid & 31, w = tid >> 5;
    int wm = w & 7, wn = w >> 3;
    int g = lane >> 2, tig = lane & 3;
    int e1 = wm*16 + g, e2 = e1 + 8;

    for (int i = tid; i < 2048; i += 1024) {
        int q = i & 3, ln = (i >> 2) & 31, pr = (i >> 7) & 1;
        int s = (i >> 8) & 1, wn_ = (i >> 9) & 3;
        int gg = ln >> 2, tt = ln & 3;
        int nt = pr*2 + (q >> 1), hb = q & 1;
        int n = (wn_*4 + nt)*8 + gg;
        int k0 = s*16 + 2*tt + hb*8;
        sW1p[i] = f2h2(ew1[(128 + k0)*128 + n], ew1[(128 + k0 + 1)*128 + n]);
    }
    for (int i = tid; i < 4096; i += 1024) {
        int q = i & 3, ln = (i >> 2) & 31;
        int s = (i >> 7) & 7, wn_ = (i >> 10) & 3;
        int gg = ln >> 2, tt = ln & 3;
        int nt = q >> 1, hb = q & 1;
        int n = (wn_*2 + nt)*8 + gg;
        int k0 = s*16 + 2*tt + hb*8;
        sW2p[i] = f2h2(ew2[k0*64 + n], ew2[(k0 + 1)*64 + n]);
    }
    for (int i = tid; i < 4096; i += 1024) {
        int q = i & 3, ln = (i >> 2) & 31, pr = (i >> 7) & 1;
        int s = (i >> 8) & 3, wn_ = (i >> 10) & 3;
        int gg = ln >> 2, tt = ln & 3;
        int nt = pr*2 + (q >> 1), hb = q & 1;
        int n = (wn_*4 + nt)*8 + gg;
        int k0 = s*16 + 2*tt + hb*8;
        sW3p[i] = f2h2(n1w1[(64 + k0)*128 + n], n1w1[(64 + k0 + 1)*128 + n]);
    }
    for (int i = tid; i < 8192; i += 1024) {
        int q = i & 3, ln = (i >> 2) & 31, pr = (i >> 7) & 1;
        int s = (i >> 8) & 7, wn_ = (i >> 11) & 3;
        int gg = ln >> 2, tt = ln & 3;
        int nt = pr*2 + (q >> 1), hb = q & 1;
        int n = (wn_*4 + nt)*8 + gg;
        int k0 = s*16 + 2*tt + hb*8;
        sW4p[i] = f2h2(n1w2[k0*128 + n], n1w2[(k0 + 1)*128 + n]);
    }
    if (tid < 64)  sB2[tid] = eb2[tid];
    if (tid < 128) sB4[tid] = n1b2[tid];

    for (int t = blockIdx.x; t < NTILE; t += gridDim.x) {
        __syncthreads();
        int e0 = t * 128;
        if (tid < 128) {
            sRow[tid] = ei[e0 + tid];
            sCol[tid] = ei[NE + e0 + tid];
        }
        if (tid < 512) {
            int e = tid >> 2, ch = tid & 3;
            float4 v0 = *(const float4*)&ea[(size_t)(e0 + e)*32 + ch*8];
            float4 v1 = *(const float4*)&ea[(size_t)(e0 + e)*32 + ch*8 + 4];
            *(uint4*)&sEA[e*20 + ch*4] = make_uint4(
                f2h2(v0.x, v0.y), f2h2(v0.z, v0.w), f2h2(v1.x, v1.y), f2h2(v1.z, v1.w));
        }
        __syncthreads();

        int r1 = sRow[e1], cc1 = sCol[e1];
        int r2 = sRow[e2], cc2 = sCol[e2];

        // GEMM1
        float acc[4][4];
        {
            const float4* P1 = (const float4*)&d_P[(size_t)r1*128 + wn*32 + tig*4];
            const float4* Q1 = (const float4*)&d_Q[(size_t)cc1*128 + wn*32 + tig*4];
            const float4* P2 = (const float4*)&d_P[(size_t)r2*128 + wn*32 + tig*4];
            const float4* Q2 = (const float4*)&d_Q[(size_t)cc2*128 + wn*32 + tig*4];
            float4 a0 = P1[0], b0 = Q1[0], a1 = P1[4], b1 = Q1[4];
            float4 c0 = P2[0], d0 = Q2[0], c1 = P2[4], d1 = Q2[4];
            acc[0][0] = a0.x + b0.x; acc[0][1] = a0.y + b0.y;
            acc[1][0] = a0.z + b0.z; acc[1][1] = a0.w + b0.w;
            acc[0][2] = c0.x + d0.x; acc[0][3] = c0.y + d0.y;
            acc[1][2] = c0.z + d0.z; acc[1][3] = c0.w + d0.w;
            acc[2][0] = a1.x + b1.x; acc[2][1] = a1.y + b1.y;
            acc[3][0] = a1.z + b1.z; acc[3][1] = a1.w + b1.w;
            acc[2][2] = c1.x + d1.x; acc[2][3] = c1.y + d1.y;
            acc[3][2] = c1.z + d1.z; acc[3][3] = c1.w + d1.w;
        }
        #pragma unroll
        for (int s = 0; s < 2; s++) {
            uint32_t a[4];
            a[0] = sEA[e1*20 + s*8 + tig];
            a[1] = sEA[e2*20 + s*8 + tig];
            a[2] = sEA[e1*20 + s*8 + tig + 4];
            a[3] = sEA[e2*20 + s*8 + tig + 4];
            uint4 b01 = *(const uint4*)&sW1p[((wn*2 + s)*2 + 0)*128 + lane*4];
            uint4 b23 = *(const uint4*)&sW1p[((wn*2 + s)*2 + 1)*128 + lane*4];
            mma16(acc[0], a, b01.x, b01.y);
            mma16(acc[1], a, b01.z, b01.w);
            mma16(acc[2], a, b23.x, b23.y);
            mma16(acc[3], a, b23.z, b23.w);
        }
        #pragma unroll
        for (int nt = 0; nt < 4; nt++) {
            int cu = wn*16 + nt*4 + tig;
            sH[e1*68 + cu] = f2h2(fmaxf(acc[nt][0], 0.f), fmaxf(acc[nt][1], 0.f));
            sH[e2*68 + cu] = f2h2(fmaxf(acc[nt][2], 0.f), fmaxf(acc[nt][3], 0.f));
        }
        __syncthreads();

        // GEMM2
        float acc2[2][4];
        #pragma unroll
        for (int nt = 0; nt < 2; nt++) {
            int c = wn*16 + nt*8 + tig*2;
            acc2[nt][0] = sB2[c]; acc2[nt][1] = sB2[c+1];
            acc2[nt][2] = sB2[c]; acc2[nt][3] = sB2[c+1];
        }
        #pragma unroll
        for (int s = 0; s < 8; s++) {
            uint32_t a[4];
            a[0] = sH[e1*68 + s*8 + tig];
            a[1] = sH[e2*68 + s*8 + tig];
            a[2] = sH[e1*68 + s*8 + tig + 4];
            a[3] = sH[e2*68 + s*8 + tig + 4];
            uint4 b = *(const uint4*)&sW2p[(wn*8 + s)*128 + lane*4];
            mma16(acc2[0], a, b.x, b.y);
            mma16(acc2[1], a, b.z, b.w);
        }
        #pragma unroll
        for (int nt = 0; nt < 2; nt++) {
            int c = wn*16 + nt*8 + tig*2;
            *(float2*)&outE[(size_t)(e0 + e1)*64 + c] = make_float2(acc2[nt][0], acc2[nt][1]);
            *(float2*)&outE[(size_t)(e0 + e2)*64 + c] = make_float2(acc2[nt][2], acc2[nt][3]);
            int cu = wn*8 + nt*4 + tig;
            sEN[e1*36 + cu] = f2h2(acc2[nt][0], acc2[nt][1]);
            sEN[e2*36 + cu] = f2h2(acc2[nt][2], acc2[nt][3]);
        }
        __syncthreads();

        // GEMM3
        {
            const float4* M1 = (const float4*)&d_Ms[(size_t)r1*128 + wn*32 + tig*4];
            const float4* M2 = (const float4*)&d_Ms[(size_t)r2*128 + wn*32 + tig*4];
            float4 a0 = M1[0], a1 = M1[4], b0 = M2[0], b1 = M2[4];
            acc[0][0] = a0.x; acc[0][1] = a0.y; acc[1][0] = a0.z; acc[1][1] = a0.w;
            acc[0][2] = b0.x; acc[0][3] = b0.y; acc[1][2] = b0.z; acc[1][3] = b0.w;
            acc[2][0] = a1.x; acc[2][1] = a1.y; acc[3][0] = a1.z; acc[3][1] = a1.w;
            acc[2][2] = b1.x; acc[2][3] = b1.y; acc[3][2] = b1.z; acc[3][3] = b1.w;
        }
        #pragma unroll
        for (int s = 0; s < 4; s++) {
            uint32_t a[4];
            a[0] = sEN[e1*36 + s*8 + tig];
            a[1] = sEN[e2*36 + s*8 + tig];
            a[2] = sEN[e1*36 + s*8 + tig + 4];
            a[3] = sEN[e2*36 + s*8 + tig + 4];
            uint4 b01 = *(const uint4*)&sW3p[((wn*4 + s)*2 + 0)*128 + lane*4];
            uint4 b23 = *(const uint4*)&sW3p[((wn*4 + s)*2 + 1)*128 + lane*4];
            mma16(acc[0], a, b01.x, b01.y);
            mma16(acc[1], a, b01.z, b01.w);
            mma16(acc[2], a, b23.x, b23.y);
            mma16(acc[3], a, b23.z, b23.w);
        }
        __syncthreads();
        #pragma unroll
        for (int nt = 0; nt < 4; nt++) {
            int cu = wn*16 + nt*4 + tig;
            sH[e1*68 + cu] = f2h2(fmaxf(acc[nt][0], 0.f), fmaxf(acc[nt][1], 0.f));
            sH[e2*68 + cu] = f2h2(fmaxf(acc[nt][2], 0.f), fmaxf(acc[nt][3], 0.f));
        }
        __syncthreads();

        // GEMM4
        float acc4[4][4];
        #pragma unroll
        for (int nt = 0; nt < 4; nt++) {
            int c = wn*32 + nt*8 + tig*2;
            acc4[nt][0] = sB4[c]; acc4[nt][1] = sB4[c+1];
            acc4[nt][2] = sB4[c]; acc4[nt][3] = sB4[c+1];
        }
        #pragma unroll
        for (int s = 0; s < 8; s++) {
            uint32_t a[4];
            a[0] = sH[e1*68 + s*8 + tig];
            a[1] = sH[e2*68 + s*8 + tig];
            a[2] = sH[e1*68 + s*8 + tig + 4];
            a[3] = sH[e2*68 + s*8 + tig + 4];
            uint4 b01 = *(const uint4*)&sW4p[((wn*8 + s)*2 + 0)*128 + lane*4];
            uint4 b23 = *(const uint4*)&sW4p[((wn*8 + s)*2 + 1)*128 + lane*4];
            mma16(acc4[0], a, b01.x, b01.y);
            mma16(acc4[1], a, b01.z, b01.w);
            mma16(acc4[2], a, b23.x, b23.y);
            mma16(acc4[3], a, b23.z, b23.w);
        }
        {
            float* p1 = &d_agg[(size_t)cc1*128 + wn*32 + tig*4];
            red_add_v4f(p1,      acc4[0][0], acc4[0][1], acc4[1][0], acc4[1][1]);
            red_add_v4f(p1 + 16, acc4[2][0], acc4[2][1], acc4[3][0], acc4[3][1]);
            float* p2 = &d_agg[(size_t)cc2*128 + wn*32 + tig*4];
            red_add_v4f(p2,      acc4[0][2], acc4[0][3], acc4[1][2], acc4[1][3]);
            red_add_v4f(p2 + 16, acc4[2][2], acc4[2][3], acc4[3][2], acc4[3][3]);
        }
    }
}

// ---------------- K3: node MLP2 + pooling via fp16 mma ----------------
// words: sW1p 13312 | sW2p 4096 | sIn 8448 [n*132] | sH 4352 [n*68] |
//        sB1 128 | sB2 64 | sInv 64 | sBat 64  = 30528 words (122 KB)
#define NODE_SMEM (30528 * 4)
__global__ void __launch_bounds__(512, 1)
k_node(const float* __restrict__ x, const float* __restrict__ u,
       const float* __restrict__ n2w1, const float* __restrict__ n2b1,
       const float* __restrict__ n2w2, const float* __restrict__ n2b2,
       const int* __restrict__ batch, float* __restrict__ outX) {
    extern __shared__ float sm[];
    uint32_t* sW1p = (uint32_t*)sm;               // 13312  [((wn*13+s)*2+pr)*128]
    uint32_t* sW2p = (uint32_t*)(sm + 13312);     // 4096
    uint32_t* sIn  = (uint32_t*)(sm + 17408);     // 8448 [n*132]
    uint32_t* sH   = (uint32_t*)(sm + 25856);     // 4352 [n*68]
    float*    sB1  = sm + 30208;                  // 128
    float*    sB2  = sm + 30336;                  // 64
    float*    sInv = sm + 30400;                  // 64
    int*      sBat = (int*)(sm + 30464);          // 64

    int tid = threadIdx.x, lane = tid & 31, w = tid >> 5;
    int wm = w & 3, wn = w >> 2;
    int g = lane >> 2, tig = lane & 3;
    int e1 = wm*16 + g, e2 = e1 + 8;

    // ---- W1 fragment staging (K=208 → 13 s-steps, N=128) ----
    for (int i = tid; i < 13312; i += 512) {
        int q = i & 3, ln = (i >> 2) & 31, pr = (i >> 7) & 1;
        int blk = i >> 8;                 // 0..51 = wn*13 + s
        int s = blk % 13, wn_ = blk / 13;
        int gg = ln >> 2, tt = ln & 3;
        int nt = pr*2 + (q >> 1), hb = q & 1;
        int n = (wn_*4 + nt)*8 + gg;
        int k0 = s*16 + 2*tt + hb*8;
        sW1p[i] = f2h2(n2w1[k0*128 + n], n2w1[(k0 + 1)*128 + n]);
    }
    // ---- W2 fragment staging (K=128 → 8 s-steps, N=64) ----
    for (int i = tid; i < 4096; i += 512) {
        int q = i & 3, ln = (i >> 2) & 31;
        int s = (i >> 7) & 7, wn_ = (i >> 10) & 3;
        int gg = ln >> 2, tt = ln & 3;
        int nt = q >> 1, hb = q & 1;
        int n = (wn_*2 + nt)*8 + gg;
        int k0 = s*16 + 2*tt + hb*8;
        sW2p[i] = f2h2(n2w2[k0*64 + n], n2w2[(k0 + 1)*64 + n]);
    }
    if (tid < 128) sB1[tid] = n2b1[tid];
    if (tid < 64)  sB2[tid] = n2b2[tid];

    int n0 = blockIdx.x * 64;
    if (tid < 64) {
        int n = n0 + tid;
        if (n < NN) { sBat[tid] = batch[n]; sInv[tid] = 1.f / fmaxf(d_deg[n], 1.f); }
        else        { sBat[tid] = 0;        sInv[tid] = 0.f; }
    }
    __syncthreads();

    // ---- stage input [64][208] fp16, stride 132 u32 (104 used) ----
    for (int i = tid; i < 64*104; i += 512) {
        int row = i / 104, c2 = i % 104;
        int n = n0 + row;
        float a = 0.f, b = 0.f;
        if (n < NN) {
            int c = 2*c2;
            #pragma unroll
            for (int j = 0; j < 2; j++) {
                int cc = c + j;
                float v;
                if (cc < 64)       v = x[(size_t)n*64 + cc];
                else if (cc < 192) v = d_agg[(size_t)n*128 + TAU16(cc - 64)] * sInv[row];
                else               v = u[sBat[row]*16 + (cc - 192)];
                if (j == 0) a = v; else b = v;
            }
        }
        sIn[row*132 + c2] = f2h2(a, b);
    }
    __syncthreads();

    // ---- GEMM1: h = relu(in @ W1 + b1)  (K=208 → 13 ks, N=128) ----
    float acc[4][4];
    #pragma unroll
    for (int nt = 0; nt < 4; nt++) {
        int c = wn*32 + nt*8 + tig*2;
        acc[nt][0] = sB1[c]; acc[nt][1] = sB1[c+1];
        acc[nt][2] = sB1[c]; acc[nt][3] = sB1[c+1];
    }
    for (int s = 0; s < 13; s++) {
        uint32_t a[4];
        a[0] = sIn[e1*132 + s*8 + tig];
        a[1] = sIn[e2*132 + s*8 + tig];
        a[2] = sIn[e1*132 + s*8 + tig + 4];
        a[3] = sIn[e2*132 + s*8 + tig + 4];
        uint4 b01 = *(const uint4*)&sW1p[((wn*13 + s)*2 + 0)*128 + lane*4];
        uint4 b23 = *(const uint4*)&sW1p[((wn*13 + s)*2 + 1)*128 + lane*4];
        mma16(acc[0], a, b01.x, b01.y);
        mma16(acc[1], a, b01.z, b01.w);
        mma16(acc[2], a, b23.x, b23.y);
        mma16(acc[3], a, b23.z, b23.w);
    }
    #pragma unroll
    for (int nt = 0; nt < 4; nt++) {
        int cu = wn*16 + nt*4 + tig;
        sH[e1*68 + cu] = f2h2(fmaxf(acc[nt][0], 0.f), fmaxf(acc[nt][1], 0.f));
        sH[e2*68 + cu] = f2h2(fmaxf(acc[nt][2], 0.f), fmaxf(acc[nt][3], 0.f));
    }
    __syncthreads();

    // ---- GEMM2: x_new = h @ W2 + b2  (K=128 → 8 ks, N=64) ----
    float acc2[2][4];
    #pragma unroll
    for (int nt = 0; nt < 2; nt++) {
        int c = wn*16 + nt*8 + tig*2;
        acc2[nt][0] = sB2[c]; acc2[nt][1] = sB2[c+1];
        acc2[nt][2] = sB2[c]; acc2[nt][3] = sB2[c+1];
    }
    #pragma unroll
    for (int s = 0; s < 8; s++) {
        uint32_t a[4];
        a[0] = sH[e1*68 + s*8 + tig];
        a[1] = sH[e2*68 + s*8 + tig];
        a[2] = sH[e1*68 + s*8 + tig + 4];
        a[3] = sH[e2*68 + s*8 + tig + 4];
        uint4 b = *(const uint4*)&sW2p[(wn*8 + s)*128 + lane*4];
        mma16(acc2[0], a, b.x, b.y);
        mma16(acc2[1], a, b.z, b.w);
    }
    #pragma unroll
    for (int nt = 0; nt < 2; nt++) {
        int c = wn*16 + nt*8 + tig*2;
        int n1n = n0 + e1, n2n = n0 + e2;
        if (n1n < NN) {
            *(float2*)&outX[(size_t)n1n*64 + c] = make_float2(acc2[nt][0], acc2[nt][1]);
            red_add_f(&d_gsum[sBat[e1]*64 + c],     acc2[nt][0]);
            red_add_f(&d_gsum[sBat[e1]*64 + c + 1], acc2[nt][1]);
        }
        if (n2n < NN) {
            *(float2*)&outX[(size_t)n2n*64 + c] = make_float2(acc2[nt][2], acc2[nt][3]);
            red_add_f(&d_gsum[sBat[e2]*64 + c],     acc2[nt][2]);
            red_add_f(&d_gsum[sBat[e2]*64 + c + 1], acc2[nt][3]);
        }
    }
}

// ---------------- K4: global MLP ----------------
__global__ void k_glob(const float* __restrict__ u,
                       const float* __restrict__ gw1, const float* __restrict__ gb1,
                       const float* __restrict__ gw2, const float* __restrict__ gb2,
                       float* __restrict__ outU) {
    __shared__ float sin[80];
    __shared__ float sh[128];
    int g = blockIdx.x, tid = threadIdx.x;
    if (tid < 16) sin[tid] = u[g*16 + tid];
    if (tid < 64) {
        float c = fmaxf(d_gcnt[g], 1.f);
        sin[16 + tid] = d_gsum[g*64 + tid] / c;
    }
    __syncthreads();
    float acc = gb1[tid];
    #pragma unroll 8
    for (int k = 0; k < 80; k++) acc += sin[k] * gw1[k*128 + tid];
    sh[tid] = fmaxf(acc, 0.f);
    __syncthreads();
    if (tid < 32) {
        float a2 = gb2[tid];
        #pragma unroll 8
        for (int k = 0; k < 128; k++) a2 += sh[k] * gw2[k*32 + tid];
        outU[g*32 + tid] = a2;
    }
}

// ---------------- launch ----------------
extern "C" void kernel_launch(void* const* d_in, const int* in_sizes, int n_in,
                              void* d_out, int out_size) {
    const float* x     = (const float*)d_in[0];
    const float* ea    = (const float*)d_in[1];
    const float* u     = (const float*)d_in[2];
    const float* ew1   = (const float*)d_in[3];
    const float* eb1   = (const float*)d_in[4];
    const float* ew2   = (const float*)d_in[5];
    const float* eb2   = (const float*)d_in[6];
    const float* n1w1  = (const float*)d_in[7];
    const float* n1b1  = (const float*)d_in[8];
    const float* n1w2  = (const float*)d_in[9];
    const float* n1b2  = (const float*)d_in[10];
    const float* n2w1  = (const float*)d_in[11];
    const float* n2b1  = (const float*)d_in[12];
    const float* n2w2  = (const float*)d_in[13];
    const float* n2b2  = (const float*)d_in[14];
    const float* gw1   = (const float*)d_in[15];
    const float* gb1   = (const float*)d_in[16];
    const float* gw2   = (const float*)d_in[17];
    const float* gb2   = (const float*)d_in[18];
    const int*   ei    = (const int*)d_in[19];
    const int*   batch = (const int*)d_in[20];

    float* out  = (float*)d_out;
    float* outX = out;
    float* outE = out + (size_t)NN*64;
    float* outU = out + (size_t)NN*64 + (size_t)NE*64;

    cudaFuncSetAttribute(k_pre,  cudaFuncAttributeMaxDynamicSharedMemorySize, PRE_SMEM);
    cudaFuncSetAttribute(k2,     cudaFuncAttributeMaxDynamicSharedMemorySize, S2_SMEM);
    cudaFuncSetAttribute(k_node, cudaFuncAttributeMaxDynamicSharedMemorySize, NODE_SMEM);

    k_zero<<<256, 256>>>();
    k_rg<<<(NG*128 + 255)/256, 256>>>(u, ew1, eb1);
    k_pre<<<(NN + 63)/64, 512, PRE_SMEM>>>(x, ew1, n1w1, n1b1, batch);
    k2<<<PGRID, 1024, S2_SMEM>>>(ea, ew1, ew2, eb2, n1w1, n1w2, n1b2, ei, outE);
    k_count<<<(NE + 255)/256, 256>>>(ei, batch);
    k_node<<<(NN + 63)/64, 512, NODE_SMEM>>>(x, u, n2w1, n2b1, n2w2, n2b2, batch, outX);
    k_glob<<<NG, 128>>>(u, gw1, gb1, gw2, gb2, outU);
}

// round 16
// speedup vs baseline: 1.4083x; 1.0593x over previous
#include <cuda_runtime.h>
#include <cstdint>

#define NN 50000
#define NE 800000
#define NG 256
#define NTILE 6250          // NE / 128
#define NTILEN 782          // ceil(NN / 64)
#define PGRID 152

typedef unsigned long long ull;

// TAU16: within 16-blocks, col (8a+2t+b) -> pos (4t+2a+b)
__host__ __device__ __forceinline__ int TAU16(int c) {
    int j = c & 15;
    return (c & ~15) | (((j >> 1) & 3) << 2) | (((j >> 3) & 1) << 1) | (j & 1);
}

// ---------------- fp16 mma.sync helpers ----------------
__device__ __forceinline__ uint32_t f2h2(float lo, float hi) {
    uint32_t r; asm("cvt.rn.f16x2.f32 %0, %1, %2;" : "=r"(r) : "f"(hi), "f"(lo)); return r;
}
__device__ __forceinline__ void mma16(float* d, const uint32_t* a, uint32_t b0, uint32_t b1) {
    asm volatile("mma.sync.aligned.m16n8k16.row.col.f32.f16.f16.f32 "
        "{%0,%1,%2,%3},{%4,%5,%6,%7},{%8,%9},{%0,%1,%2,%3};"
        : "+f"(d[0]), "+f"(d[1]), "+f"(d[2]), "+f"(d[3])
        : "r"(a[0]), "r"(a[1]), "r"(a[2]), "r"(a[3]), "r"(b0), "r"(b1));
}
__device__ __forceinline__ void red_add_v4f(float* p, float a, float b, float c, float d) {
    asm volatile("red.global.add.v4.f32 [%0], {%1,%2,%3,%4};" :: "l"(p), "f"(a), "f"(b), "f"(c), "f"(d) : "memory");
}
__device__ __forceinline__ void red_add_f(float* p, float a) {
    asm volatile("red.global.add.f32 [%0], %1;" :: "l"(p), "f"(a) : "memory");
}

// ---------------- device scratch ----------------
__device__ float d_P [NN*128];   // (x@e_w1[:64] + Rg[batch] + eb1), TAU16 layout
__device__ float d_Q [NN*128];   // TAU16 layout
__device__ float d_Ms[NN*128];   // TAU16 layout
__device__ float d_Rg[NG*128];   // TAU16 layout, eb1 folded in
__device__ float d_agg[NN*128];  // TAU16 layout
__device__ float d_deg[NN];
__device__ float d_gsum[NG*64];
__device__ float d_gcnt[NG];

// ---------------- K0 ----------------
__global__ void k_zero() {
    int i = blockIdx.x * blockDim.x + threadIdx.x;
    int stride = gridDim.x * blockDim.x;
    for (int idx = i; idx < NN*128; idx += stride) d_agg[idx] = 0.f;
    for (int idx = i; idx < NN;     idx += stride) d_deg[idx] = 0.f;
    for (int idx = i; idx < NG*64;  idx += stride) d_gsum[idx] = 0.f;
    for (int idx = i; idx < NG;     idx += stride) d_gcnt[idx] = 0.f;
}

// ---------------- K1b: Rg_tau = TAU16(u @ e_w1[160:176] + eb1) ----------------
__global__ void k_rg(const float* __restrict__ u, const float* __restrict__ ew1,
                     const float* __restrict__ eb1) {
    int i = blockIdx.x * blockDim.x + threadIdx.x;
    if (i < NG*128) {
        int g = i >> 7, j = i & 127;
        float acc = eb1[j];
        #pragma unroll
        for (int k = 0; k < 16; k++) acc += u[g*16 + k] * ew1[(160 + k)*128 + j];
        d_Rg[g*128 + TAU16(j)] = acc;
    }
}

// ---------------- K1: persistent precompute P, Q, Ms via fp16 mma (+gcnt) ----------------
// words: sWa 4096 | sWb 4096 | sWm 4096 | sX 2304 [n*36] | sBmt 128 | sBat 64 = 14784
#define PRE_SMEM (14784 * 4)
__global__ void __launch_bounds__(512, 1)
k_pre(const float* __restrict__ x, const float* __restrict__ ew1,
      const float* __restrict__ n1w1, const float* __restrict__ n1b1,
      const int* __restrict__ batch) {
    extern __shared__ float sm[];
    uint32_t* sWa  = (uint32_t*)sm;
    uint32_t* sWb  = (uint32_t*)(sm + 4096);
    uint32_t* sWm  = (uint32_t*)(sm + 8192);
    uint32_t* sX   = (uint32_t*)(sm + 12288);     // [n*36]
    float*    sBmt = sm + 14592;
    int*      sBat = (int*)(sm + 14720);

    int tid = threadIdx.x, lane = tid & 31, w = tid >> 5;
    int wm = w & 3, wn = w >> 2;
    int g = lane >> 2, tig = lane & 3;
    int e1 = wm*16 + g, e2 = e1 + 8;

    // ---- one-time weight fragment staging (K=64 → 4 s-steps, N=128) ----
    for (int i = tid; i < 4096; i += 512) {
        int q = i & 3, ln = (i >> 2) & 31, pr = (i >> 7) & 1;
        int s = (i >> 8) & 3, wn_ = (i >> 10) & 3;
        int gg = ln >> 2, tt = ln & 3;
        int nt = pr*2 + (q >> 1), hb = q & 1;
        int n = (wn_*4 + nt)*8 + gg;
        int k0 = s*16 + 2*tt + hb*8;
        sWa[i] = f2h2(ew1[k0*128 + n],        ew1[(k0 + 1)*128 + n]);
        sWb[i] = f2h2(ew1[(64 + k0)*128 + n], ew1[(64 + k0 + 1)*128 + n]);
        sWm[i] = f2h2(n1w1[k0*128 + n],       n1w1[(k0 + 1)*128 + n]);
    }
    if (tid < 128) sBmt[TAU16(tid)] = n1b1[tid];

    for (int t = blockIdx.x; t < NTILEN; t += gridDim.x) {
        __syncthreads();   // previous-tile sX/sBat reads done
        int n0 = t * 64;
        if (tid < 64) {
            int n = n0 + tid;
            int b = (n < NN) ? batch[n] : 0;
            sBat[tid] = b;
            if (n < NN) red_add_f(&d_gcnt[b], 1.f);   // fold k_count's gcnt here
        }
        for (int i = tid; i < 64*32; i += 512) {
            int row = i >> 5, c2 = i & 31;
            int n = n0 + row;
            float a = 0.f, b = 0.f;
            if (n < NN) { a = x[(size_t)n*64 + 2*c2]; b = x[(size_t)n*64 + 2*c2 + 1]; }
            sX[row*36 + c2] = f2h2(a, b);
        }
        __syncthreads();

        for (int which = 0; which < 3; which++) {
            const uint32_t* W = (which == 0) ? sWa : (which == 1) ? sWb : sWm;
            float acc[4][4];
            #pragma unroll
            for (int nt = 0; nt < 4; nt++)
                #pragma unroll
                for (int j = 0; j < 4; j++) acc[nt][j] = 0.f;
            #pragma unroll
            for (int s = 0; s < 4; s++) {
                uint32_t a[4];
                a[0] = sX[e1*36 + s*8 + tig];
                a[1] = sX[e2*36 + s*8 + tig];
                a[2] = sX[e1*36 + s*8 + tig + 4];
                a[3] = sX[e2*36 + s*8 + tig + 4];
                uint4 b01 = *(const uint4*)&W[((wn*4 + s)*2 + 0)*128 + lane*4];
                uint4 b23 = *(const uint4*)&W[((wn*4 + s)*2 + 1)*128 + lane*4];
                mma16(acc[0], a, b01.x, b01.y);
                mma16(acc[1], a, b01.z, b01.w);
                mma16(acc[2], a, b23.x, b23.y);
                mma16(acc[3], a, b23.z, b23.w);
            }
            float* dst = (which == 0) ? d_P : (which == 1) ? d_Q : d_Ms;
            int pos = wn*32 + tig*4;
            #pragma unroll
            for (int half = 0; half < 2; half++) {
                int e = half ? e2 : e1;
                int n = n0 + e;
                if (n >= NN) continue;
                int o = half ? 2 : 0;
                float4 v0 = make_float4(acc[0][o], acc[0][o+1], acc[1][o], acc[1][o+1]);
                float4 v1 = make_float4(acc[2][o], acc[2][o+1], acc[3][o], acc[3][o+1]);
                if (which == 0) {
                    const float4* rg = (const float4*)&d_Rg[(size_t)sBat[e]*128 + pos];
                    float4 r0 = rg[0], r1 = rg[4];
                    v0.x += r0.x; v0.y += r0.y; v0.z += r0.z; v0.w += r0.w;
                    v1.x += r1.x; v1.y += r1.y; v1.z += r1.z; v1.w += r1.w;
                } else if (which == 2) {
                    const float4* bm = (const float4*)&sBmt[pos];
                    float4 r0 = bm[0], r1 = bm[4];
                    v0.x += r0.x; v0.y += r0.y; v0.z += r0.z; v0.w += r0.w;
                    v1.x += r1.x; v1.y += r1.y; v1.z += r1.z; v1.w += r1.w;
                }
                *(float4*)&dst[(size_t)n*128 + pos]      = v0;
                *(float4*)&dst[(size_t)n*128 + pos + 16] = v1;
            }
        }
    }
}

// ================= K2: merged edge pipeline — persistent, 1024 thr, split H buffers =================
// words: sW1p 2048 | sW2p 4096 | sW3p 4096 | sW4p 8192 | sEA 2560 | sEN 4608 |
//        sH1 8704 | sH2 8704 | sB2 64 | sB4 128 | idx 256  = 43456 words (173.8 KB)
#define S2_SMEM (43456 * 4)
__global__ void __launch_bounds__(1024, 1)
k2(const float* __restrict__ ea, const float* __restrict__ ew1,
   const float* __restrict__ ew2, const float* __restrict__ eb2,
   const float* __restrict__ n1w1, const float* __restrict__ n1w2,
   const float* __restrict__ n1b2,
   const int* __restrict__ ei, float* __restrict__ outE) {
    extern __shared__ float sm[];
    uint32_t* sW1p = (uint32_t*)sm;               // 2048
    uint32_t* sW2p = (uint32_t*)(sm + 2048);      // 4096
    uint32_t* sW3p = (uint32_t*)(sm + 6144);      // 4096
    uint32_t* sW4p = (uint32_t*)(sm + 10240);     // 8192
    uint32_t* sEA  = (uint32_t*)(sm + 18432);     // 2560  [e*20]
    uint32_t* sEN  = (uint32_t*)(sm + 20992);     // 4608  [e*36]
    uint32_t* sH1  = (uint32_t*)(sm + 25600);     // 8704  [e*68]
    uint32_t* sH2  = (uint32_t*)(sm + 34304);     // 8704  [e*68]
    float*    sB2  = sm + 43008;
    float*    sB4  = sm + 43072;
    int* sRow = (int*)(sm + 43200);
    int* sCol = sRow + 128;

    int tid = threadIdx.x, lane = tid & 31, w = tid >> 5;
    int wm = w & 7, wn = w >> 3;
    int g = lane >> 2, tig = lane & 3;
    int e1 = wm*16 + g, e2 = e1 + 8;

    for (int i = tid; i < 2048; i += 1024) {
        int q = i & 3, ln = (i >> 2) & 31, pr = (i >> 7) & 1;
        int s = (i >> 8) & 1, wn_ = (i >> 9) & 3;
        int gg = ln >> 2, tt = ln & 3;
        int nt = pr*2 + (q >> 1), hb = q & 1;
        int n = (wn_*4 + nt)*8 + gg;
        int k0 = s*16 + 2*tt + hb*8;
        sW1p[i] = f2h2(ew1[(128 + k0)*128 + n], ew1[(128 + k0 + 1)*128 + n]);
    }
    for (int i = tid; i < 4096; i += 1024) {
        int q = i & 3, ln = (i >> 2) & 31;
        int s = (i >> 7) & 7, wn_ = (i >> 10) & 3;
        int gg = ln >> 2, tt = ln & 3;
        int nt = q >> 1, hb = q & 1;
        int n = (wn_*2 + nt)*8 + gg;
        int k0 = s*16 + 2*tt + hb*8;
        sW2p[i] = f2h2(ew2[k0*64 + n], ew2[(k0 + 1)*64 + n]);
    }
    for (int i = tid; i < 4096; i += 1024) {
        int q = i & 3, ln = (i >> 2) & 31, pr = (i >> 7) & 1;
        int s = (i >> 8) & 3, wn_ = (i >> 10) & 3;
        int gg = ln >> 2, tt = ln & 3;
        int nt = pr*2 + (q >> 1), hb = q & 1;
        int n = (wn_*4 + nt)*8 + gg;
        int k0 = s*16 + 2*tt + hb*8;
        sW3p[i] = f2h2(n1w1[(64 + k0)*128 + n], n1w1[(64 + k0 + 1)*128 + n]);
    }
    for (int i = tid; i < 8192; i += 1024) {
        int q = i & 3, ln = (i >> 2) & 31, pr = (i >> 7) & 1;
        int s = (i >> 8) & 7, wn_ = (i >> 11) & 3;
        int gg = ln >> 2, tt = ln & 3;
        int nt = pr*2 + (q >> 1), hb = q & 1;
        int n = (wn_*4 + nt)*8 + gg;
        int k0 = s*16 + 2*tt + hb*8;
        sW4p[i] = f2h2(n1w2[k0*128 + n], n1w2[(k0 + 1)*128 + n]);
    }
    if (tid < 64)  sB2[tid] = eb2[tid];
    if (tid < 128) sB4[tid] = n1b2[tid];

    for (int t = blockIdx.x; t < NTILE; t += gridDim.x) {
        __syncthreads();
        int e0 = t * 128;
        if (tid < 128) {
            int rr = ei[e0 + tid], cc = ei[NE + e0 + tid];
            sRow[tid] = rr; sCol[tid] = cc;
            red_add_f(&d_deg[cc], 1.f);       // fold k_count's deg here (each edge once)
        }
        if (tid < 512) {
            int e = tid >> 2, ch = tid & 3;
            float4 v0 = *(const float4*)&ea[(size_t)(e0 + e)*32 + ch*8];
            float4 v1 = *(const float4*)&ea[(size_t)(e0 + e)*32 + ch*8 + 4];
            *(uint4*)&sEA[e*20 + ch*4] = make_uint4(
                f2h2(v0.x, v0.y), f2h2(v0.z, v0.w), f2h2(v1.x, v1.y), f2h2(v1.z, v1.w));
        }
        __syncthreads();

        int r1 = sRow[e1], cc1 = sCol[e1];
        int r2 = sRow[e2], cc2 = sCol[e2];

        // GEMM1: H1 = relu(PR[row] + Q[col] + EA @ W1c)
        float acc[4][4];
        {
            const float4* P1 = (const float4*)&d_P[(size_t)r1*128 + wn*32 + tig*4];
            const float4* Q1 = (const float4*)&d_Q[(size_t)cc1*128 + wn*32 + tig*4];
            const float4* P2 = (const float4*)&d_P[(size_t)r2*128 + wn*32 + tig*4];
            const float4* Q2 = (const float4*)&d_Q[(size_t)cc2*128 + wn*32 + tig*4];
            float4 a0 = P1[0], b0 = Q1[0], a1 = P1[4], b1 = Q1[4];
            float4 c0 = P2[0], d0 = Q2[0], c1 = P2[4], d1 = Q2[4];
            acc[0][0] = a0.x + b0.x; acc[0][1] = a0.y + b0.y;
            acc[1][0] = a0.z + b0.z; acc[1][1] = a0.w + b0.w;
            acc[0][2] = c0.x + d0.x; acc[0][3] = c0.y + d0.y;
            acc[1][2] = c0.z + d0.z; acc[1][3] = c0.w + d0.w;
            acc[2][0] = a1.x + b1.x; acc[2][1] = a1.y + b1.y;
            acc[3][0] = a1.z + b1.z; acc[3][1] = a1.w + b1.w;
            acc[2][2] = c1.x + d1.x; acc[2][3] = c1.y + d1.y;
            acc[3][2] = c1.z + d1.z; acc[3][3] = c1.w + d1.w;
        }
        #pragma unroll
        for (int s = 0; s < 2; s++) {
            uint32_t a[4];
            a[0] = sEA[e1*20 + s*8 + tig];
            a[1] = sEA[e2*20 + s*8 + tig];
            a[2] = sEA[e1*20 + s*8 + tig + 4];
            a[3] = sEA[e2*20 + s*8 + tig + 4];
            uint4 b01 = *(const uint4*)&sW1p[((wn*2 + s)*2 + 0)*128 + lane*4];
            uint4 b23 = *(const uint4*)&sW1p[((wn*2 + s)*2 + 1)*128 + lane*4];
            mma16(acc[0], a, b01.x, b01.y);
            mma16(acc[1], a, b01.z, b01.w);
            mma16(acc[2], a, b23.x, b23.y);
            mma16(acc[3], a, b23.z, b23.w);
        }
        #pragma unroll
        for (int nt = 0; nt < 4; nt++) {
            int cu = wn*16 + nt*4 + tig;
            sH1[e1*68 + cu] = f2h2(fmaxf(acc[nt][0], 0.f), fmaxf(acc[nt][1], 0.f));
            sH1[e2*68 + cu] = f2h2(fmaxf(acc[nt][2], 0.f), fmaxf(acc[nt][3], 0.f));
        }
        __syncthreads();

        // GEMM2: EN = H1 @ W2 + b2 → outE + sEN
        float acc2[2][4];
        #pragma unroll
        for (int nt = 0; nt < 2; nt++) {
            int c = wn*16 + nt*8 + tig*2;
            acc2[nt][0] = sB2[c]; acc2[nt][1] = sB2[c+1];
            acc2[nt][2] = sB2[c]; acc2[nt][3] = sB2[c+1];
        }
        #pragma unroll
        for (int s = 0; s < 8; s++) {
            uint32_t a[4];
            a[0] = sH1[e1*68 + s*8 + tig];
            a[1] = sH1[e2*68 + s*8 + tig];
            a[2] = sH1[e1*68 + s*8 + tig + 4];
            a[3] = sH1[e2*68 + s*8 + tig + 4];
            uint4 b = *(const uint4*)&sW2p[(wn*8 + s)*128 + lane*4];
            mma16(acc2[0], a, b.x, b.y);
            mma16(acc2[1], a, b.z, b.w);
        }
        #pragma unroll
        for (int nt = 0; nt < 2; nt++) {
            int c = wn*16 + nt*8 + tig*2;
            *(float2*)&outE[(size_t)(e0 + e1)*64 + c] = make_float2(acc2[nt][0], acc2[nt][1]);
            *(float2*)&outE[(size_t)(e0 + e2)*64 + c] = make_float2(acc2[nt][2], acc2[nt][3]);
            int cu = wn*8 + nt*4 + tig;
            sEN[e1*36 + cu] = f2h2(acc2[nt][0], acc2[nt][1]);
            sEN[e2*36 + cu] = f2h2(acc2[nt][2], acc2[nt][3]);
        }
        __syncthreads();

        // GEMM3: H2 = relu(Ms[row] + EN @ W3)  (separate buffer: no mid-phase barrier)
        {
            const float4* M1 = (const float4*)&d_Ms[(size_t)r1*128 + wn*32 + tig*4];
            const float4* M2 = (const float4*)&d_Ms[(size_t)r2*128 + wn*32 + tig*4];
            float4 a0 = M1[0], a1 = M1[4], b0 = M2[0], b1 = M2[4];
            acc[0][0] = a0.x; acc[0][1] = a0.y; acc[1][0] = a0.z; acc[1][1] = a0.w;
            acc[0][2] = b0.x; acc[0][3] = b0.y; acc[1][2] = b0.z; acc[1][3] = b0.w;
            acc[2][0] = a1.x; acc[2][1] = a1.y; acc[3][0] = a1.z; acc[3][1] = a1.w;
            acc[2][2] = b1.x; acc[2][3] = b1.y; acc[3][2] = b1.z; acc[3][3] = b1.w;
        }
        #pragma unroll
        for (int s = 0; s < 4; s++) {
            uint32_t a[4];
            a[0] = sEN[e1*36 + s*8 + tig];
            a[1] = sEN[e2*36 + s*8 + tig];
            a[2] = sEN[e1*36 + s*8 + tig + 4];
            a[3] = sEN[e2*36 + s*8 + tig + 4];
            uint4 b01 = *(const uint4*)&sW3p[((wn*4 + s)*2 + 0)*128 + lane*4];
            uint4 b23 = *(const uint4*)&sW3p[((wn*4 + s)*2 + 1)*128 + lane*4];
            mma16(acc[0], a, b01.x, b01.y);
            mma16(acc[1], a, b01.z, b01.w);
            mma16(acc[2], a, b23.x, b23.y);
            mma16(acc[3], a, b23.z, b23.w);
        }
        #pragma unroll
        for (int nt = 0; nt < 4; nt++) {
            int cu = wn*16 + nt*4 + tig;
            sH2[e1*68 + cu] = f2h2(fmaxf(acc[nt][0], 0.f), fmaxf(acc[nt][1], 0.f));
            sH2[e2*68 + cu] = f2h2(fmaxf(acc[nt][2], 0.f), fmaxf(acc[nt][3], 0.f));
        }
        __syncthreads();

        // GEMM4: m = H2 @ W4 + b4 → TAU16 v4 scatter
        float acc4[4][4];
        #pragma unroll
        for (int nt = 0; nt < 4; nt++) {
            int c = wn*32 + nt*8 + tig*2;
            acc4[nt][0] = sB4[c]; acc4[nt][1] = sB4[c+1];
            acc4[nt][2] = sB4[c]; acc4[nt][3] = sB4[c+1];
        }
        #pragma unroll
        for (int s = 0; s < 8; s++) {
            uint32_t a[4];
            a[0] = sH2[e1*68 + s*8 + tig];
            a[1] = sH2[e2*68 + s*8 + tig];
            a[2] = sH2[e1*68 + s*8 + tig + 4];
            a[3] = sH2[e2*68 + s*8 + tig + 4];
            uint4 b01 = *(const uint4*)&sW4p[((wn*8 + s)*2 + 0)*128 + lane*4];
            uint4 b23 = *(const uint4*)&sW4p[((wn*8 + s)*2 + 1)*128 + lane*4];
            mma16(acc4[0], a, b01.x, b01.y);
            mma16(acc4[1], a, b01.z, b01.w);
            mma16(acc4[2], a, b23.x, b23.y);
            mma16(acc4[3], a, b23.z, b23.w);
        }
        {
            float* p1 = &d_agg[(size_t)cc1*128 + wn*32 + tig*4];
            red_add_v4f(p1,      acc4[0][0], acc4[0][1], acc4[1][0], acc4[1][1]);
            red_add_v4f(p1 + 16, acc4[2][0], acc4[2][1], acc4[3][0], acc4[3][1]);
            float* p2 = &d_agg[(size_t)cc2*128 + wn*32 + tig*4];
            red_add_v4f(p2,      acc4[0][2], acc4[0][3], acc4[1][2], acc4[1][3]);
            red_add_v4f(p2 + 16, acc4[2][2], acc4[2][3], acc4[3][2], acc4[3][3]);
        }
    }
}

// ---------------- K3: persistent node MLP2 + pooling via fp16 mma ----------------
// words: sW1p 13312 | sW2p 4096 | sIn 8448 [n*132] | sH 4352 [n*68] |
//        sB1 128 | sB2 64 | sInv 64 | sBat 64  = 30528 words (122 KB)
#define NODE_SMEM (30528 * 4)
__global__ void __launch_bounds__(512, 1)
k_node(const float* __restrict__ x, const float* __restrict__ u,
       const float* __restrict__ n2w1, const float* __restrict__ n2b1,
       const float* __restrict__ n2w2, const float* __restrict__ n2b2,
       const int* __restrict__ batch, float* __restrict__ outX) {
    extern __shared__ float sm[];
    uint32_t* sW1p = (uint32_t*)sm;               // 13312
    uint32_t* sW2p = (uint32_t*)(sm + 13312);     // 4096
    uint32_t* sIn  = (uint32_t*)(sm + 17408);     // 8448 [n*132]
    uint32_t* sH   = (uint32_t*)(sm + 25856);     // 4352 [n*68]
    float*    sB1  = sm + 30208;
    float*    sB2  = sm + 30336;
    float*    sInv = sm + 30400;
    int*      sBat = (int*)(sm + 30464);

    int tid = threadIdx.x, lane = tid & 31, w = tid >> 5;
    int wm = w & 3, wn = w >> 2;
    int g = lane >> 2, tig = lane & 3;
    int e1 = wm*16 + g, e2 = e1 + 8;

    // ---- one-time weight staging ----
    for (int i = tid; i < 13312; i += 512) {
        int q = i & 3, ln = (i >> 2) & 31, pr = (i >> 7) & 1;
        int blk = i >> 8;
        int s = blk % 13, wn_ = blk / 13;
        int gg = ln >> 2, tt = ln & 3;
        int nt = pr*2 + (q >> 1), hb = q & 1;
        int n = (wn_*4 + nt)*8 + gg;
        int k0 = s*16 + 2*tt + hb*8;
        sW1p[i] = f2h2(n2w1[k0*128 + n], n2w1[(k0 + 1)*128 + n]);
    }
    for (int i = tid; i < 4096; i += 512) {
        int q = i & 3, ln = (i >> 2) & 31;
        int s = (i >> 7) & 7, wn_ = (i >> 10) & 3;
        int gg = ln >> 2, tt = ln & 3;
        int nt = q >> 1, hb = q & 1;
        int n = (wn_*2 + nt)*8 + gg;
        int k0 = s*16 + 2*tt + hb*8;
        sW2p[i] = f2h2(n2w2[k0*64 + n], n2w2[(k0 + 1)*64 + n]);
    }
    if (tid < 128) sB1[tid] = n2b1[tid];
    if (tid < 64)  sB2[tid] = n2b2[tid];

    for (int t = blockIdx.x; t < NTILEN; t += gridDim.x) {
        __syncthreads();   // previous-tile reads done
        int n0 = t * 64;
        if (tid < 64) {
            int n = n0 + tid;
            if (n < NN) { sBat[tid] = batch[n]; sInv[tid] = 1.f / fmaxf(d_deg[n], 1.f); }
            else        { sBat[tid] = 0;        sInv[tid] = 0.f; }
        }
        __syncthreads();   // sInv ready for staging

        for (int i = tid; i < 64*104; i += 512) {
            int row = i / 104, c2 = i % 104;
            int n = n0 + row;
            float a = 0.f, b = 0.f;
            if (n < NN) {
                int c = 2*c2;
                #pragma unroll
                for (int j = 0; j < 2; j++) {
                    int cc = c + j;
                    float v;
                    if (cc < 64)       v = x[(size_t)n*64 + cc];
                    else if (cc < 192) v = d_agg[(size_t)n*128 + TAU16(cc - 64)] * sInv[row];
                    else               v = u[sBat[row]*16 + (cc - 192)];
                    if (j == 0) a = v; else b = v;
                }
            }
            sIn[row*132 + c2] = f2h2(a, b);
        }
        __syncthreads();

        // GEMM1: h = relu(in @ W1 + b1)
        float acc[4][4];
        #pragma unroll
        for (int nt = 0; nt < 4; nt++) {
            int c = wn*32 + nt*8 + tig*2;
            acc[nt][0] = sB1[c]; acc[nt][1] = sB1[c+1];
            acc[nt][2] = sB1[c]; acc[nt][3] = sB1[c+1];
        }
        for (int s = 0; s < 13; s++) {
            uint32_t a[4];
            a[0] = sIn[e1*132 + s*8 + tig];
            a[1] = sIn[e2*132 + s*8 + tig];
            a[2] = sIn[e1*132 + s*8 + tig + 4];
            a[3] = sIn[e2*132 + s*8 + tig + 4];
            uint4 b01 = *(const uint4*)&sW1p[((wn*13 + s)*2 + 0)*128 + lane*4];
            uint4 b23 = *(const uint4*)&sW1p[((wn*13 + s)*2 + 1)*128 + lane*4];
            mma16(acc[0], a, b01.x, b01.y);
            mma16(acc[1], a, b01.z, b01.w);
            mma16(acc[2], a, b23.x, b23.y);
            mma16(acc[3], a, b23.z, b23.w);
        }
        #pragma unroll
        for (int nt = 0; nt < 4; nt++) {
            int cu = wn*16 + nt*4 + tig;
            sH[e1*68 + cu] = f2h2(fmaxf(acc[nt][0], 0.f), fmaxf(acc[nt][1], 0.f));
            sH[e2*68 + cu] = f2h2(fmaxf(acc[nt][2], 0.f), fmaxf(acc[nt][3], 0.f));
        }
        __syncthreads();

        // GEMM2: x_new = h @ W2 + b2
        float acc2[2][4];
        #pragma unroll
        for (int nt = 0; nt < 2; nt++) {
            int c = wn*16 + nt*8 + tig*2;
            acc2[nt][0] = sB2[c]; acc2[nt][1] = sB2[c+1];
            acc2[nt][2] = sB2[c]; acc2[nt][3] = sB2[c+1];
        }
        #pragma unroll
        for (int s = 0; s < 8; s++) {
            uint32_t a[4];
            a[0] = sH[e1*68 + s*8 + tig];
            a[1] = sH[e2*68 + s*8 + tig];
            a[2] = sH[e1*68 + s*8 + tig + 4];
            a[3] = sH[e2*68 + s*8 + tig + 4];
            uint4 b = *(const uint4*)&sW2p[(wn*8 + s)*128 + lane*4];
            mma16(acc2[0], a, b.x, b.y);
            mma16(acc2[1], a, b.z, b.w);
        }
        #pragma unroll
        for (int nt = 0; nt < 2; nt++) {
            int c = wn*16 + nt*8 + tig*2;
            int n1n = n0 + e1, n2n = n0 + e2;
            if (n1n < NN) {
                *(float2*)&outX[(size_t)n1n*64 + c] = make_float2(acc2[nt][0], acc2[nt][1]);
                red_add_f(&d_gsum[sBat[e1]*64 + c],     acc2[nt][0]);
                red_add_f(&d_gsum[sBat[e1]*64 + c + 1], acc2[nt][1]);
            }
            if (n2n < NN) {
                *(float2*)&outX[(size_t)n2n*64 + c] = make_float2(acc2[nt][2], acc2[nt][3]);
                red_add_f(&d_gsum[sBat[e2]*64 + c],     acc2[nt][2]);
                red_add_f(&d_gsum[sBat[e2]*64 + c + 1], acc2[nt][3]);
            }
        }
    }
}

// ---------------- K4: global MLP ----------------
__global__ void k_glob(const float* __restrict__ u,
                       const float* __restrict__ gw1, const float* __restrict__ gb1,
                       const float* __restrict__ gw2, const float* __restrict__ gb2,
                       float* __restrict__ outU) {
    __shared__ float sin[80];
    __shared__ float sh[128];
    int g = blockIdx.x, tid = threadIdx.x;
    if (tid < 16) sin[tid] = u[g*16 + tid];
    if (tid < 64) {
        float c = fmaxf(d_gcnt[g], 1.f);
        sin[16 + tid] = d_gsum[g*64 + tid] / c;
    }
    __syncthreads();
    float acc = gb1[tid];
    #pragma unroll 8
    for (int k = 0; k < 80; k++) acc += sin[k] * gw1[k*128 + tid];
    sh[tid] = fmaxf(acc, 0.f);
    __syncthreads();
    if (tid < 32) {
        float a2 = gb2[tid];
        #pragma unroll 8
        for (int k = 0; k < 128; k++) a2 += sh[k] * gw2[k*32 + tid];
        outU[g*32 + tid] = a2;
    }
}

// ---------------- launch ----------------
extern "C" void kernel_launch(void* const* d_in, const int* in_sizes, int n_in,
                              void* d_out, int out_size) {
    const float* x     = (const float*)d_in[0];
    const float* ea    = (const float*)d_in[1];
    const float* u     = (const float*)d_in[2];
    const float* ew1   = (const float*)d_in[3];
    const float* eb1   = (const float*)d_in[4];
    const float* ew2   = (const float*)d_in[5];
    const float* eb2   = (const float*)d_in[6];
    const float* n1w1  = (const float*)d_in[7];
    const float* n1b1  = (const float*)d_in[8];
    const float* n1w2  = (const float*)d_in[9];
    const float* n1b2  = (const float*)d_in[10];
    const float* n2w1  = (const float*)d_in[11];
    const float* n2b1  = (const float*)d_in[12];
    const float* n2w2  = (const float*)d_in[13];
    const float* n2b2  = (const float*)d_in[14];
    const float* gw1   = (const float*)d_in[15];
    const float* gb1   = (const float*)d_in[16];
    const float* gw2   = (const float*)d_in[17];
    const float* gb2   = (const float*)d_in[18];
    const int*   ei    = (const int*)d_in[19];
    const int*   batch = (const int*)d_in[20];

    float* out  = (float*)d_out;
    float* outX = out;
    float* outE = out + (size_t)NN*64;
    float* outU = out + (size_t)NN*64 + (size_t)NE*64;

    cudaFuncSetAttribute(k_pre,  cudaFuncAttributeMaxDynamicSharedMemorySize, PRE_SMEM);
    cudaFuncSetAttribute(k2,     cudaFuncAttributeMaxDynamicSharedMemorySize, S2_SMEM);
    cudaFuncSetAttribute(k_node, cudaFuncAttributeMaxDynamicSharedMemorySize, NODE_SMEM);

    k_zero<<<256, 256>>>();
    k_rg<<<(NG*128 + 255)/256, 256>>>(u, ew1, eb1);
    k_pre<<<PGRID, 512, PRE_SMEM>>>(x, ew1, n1w1, n1b1, batch);
    k2<<<PGRID, 1024, S2_SMEM>>>(ea, ew1, ew2, eb2, n1w1, n1w2, n1b2, ei, outE);
    k_node<<<PGRID, 512, NODE_SMEM>>>(x, u, n2w1, n2b1, n2w2, n2b2, batch, outX);
    k_glob<<<NG, 128>>>(u, gw1, gb1, gw2, gb2, outU);
}

// round 17
// speedup vs baseline: 1.6965x; 1.2046x over previous
#include <cuda_runtime.h>
#include <cstdint>

#define NN 50000
#define NE 800000
#define NG 256
#define NTILE16 50000       // NE / 16 (per-group tiles)
#define NTILEN 782          // ceil(NN / 64)
#define PGRID 152

typedef unsigned long long ull;

// TAU16: within 16-blocks, col (8a+2t+b) -> pos (4t+2a+b)
__host__ __device__ __forceinline__ int TAU16(int c) {
    int j = c & 15;
    return (c & ~15) | (((j >> 1) & 3) << 2) | (((j >> 3) & 1) << 1) | (j & 1);
}

// ---------------- fp16 mma.sync helpers ----------------
__device__ __forceinline__ uint32_t f2h2(float lo, float hi) {
    uint32_t r; asm("cvt.rn.f16x2.f32 %0, %1, %2;" : "=r"(r) : "f"(hi), "f"(lo)); return r;
}
__device__ __forceinline__ void mma16(float* d, const uint32_t* a, uint32_t b0, uint32_t b1) {
    asm volatile("mma.sync.aligned.m16n8k16.row.col.f32.f16.f16.f32 "
        "{%0,%1,%2,%3},{%4,%5,%6,%7},{%8,%9},{%0,%1,%2,%3};"
        : "+f"(d[0]), "+f"(d[1]), "+f"(d[2]), "+f"(d[3])
        : "r"(a[0]), "r"(a[1]), "r"(a[2]), "r"(a[3]), "r"(b0), "r"(b1));
}
__device__ __forceinline__ void gbar(int id) {    // 128-thread named barrier
    asm volatile("bar.sync %0, 128;" :: "r"(id) : "memory");
}
__device__ __forceinline__ void red_add_v4f(float* p, float a, float b, float c, float d) {
    asm volatile("red.global.add.v4.f32 [%0], {%1,%2,%3,%4};" :: "l"(p), "f"(a), "f"(b), "f"(c), "f"(d) : "memory");
}
__device__ __forceinline__ void red_add_f(float* p, float a) {
    asm volatile("red.global.add.f32 [%0], %1;" :: "l"(p), "f"(a) : "memory");
}

// ---------------- device scratch ----------------
__device__ float d_P [NN*128];   // (x@e_w1[:64] + Rg[batch] + eb1), TAU16 layout
__device__ float d_Q [NN*128];   // TAU16 layout
__device__ float d_Ms[NN*128];   // TAU16 layout
__device__ float d_Rg[NG*128];   // TAU16 layout, eb1 folded in
__device__ float d_agg[NN*128];  // TAU16 layout
__device__ float d_deg[NN];
__device__ float d_gsum[NG*64];
__device__ float d_gcnt[NG];

// ---------------- K0 ----------------
__global__ void k_zero() {
    int i = blockIdx.x * blockDim.x + threadIdx.x;
    int stride = gridDim.x * blockDim.x;
    for (int idx = i; idx < NN*128; idx += stride) d_agg[idx] = 0.f;
    for (int idx = i; idx < NN;     idx += stride) d_deg[idx] = 0.f;
    for (int idx = i; idx < NG*64;  idx += stride) d_gsum[idx] = 0.f;
    for (int idx = i; idx < NG;     idx += stride) d_gcnt[idx] = 0.f;
}

// ---------------- K1b: Rg_tau = TAU16(u @ e_w1[160:176] + eb1) ----------------
__global__ void k_rg(const float* __restrict__ u, const float* __restrict__ ew1,
                     const float* __restrict__ eb1) {
    int i = blockIdx.x * blockDim.x + threadIdx.x;
    if (i < NG*128) {
        int g = i >> 7, j = i & 127;
        float acc = eb1[j];
        #pragma unroll
        for (int k = 0; k < 16; k++) acc += u[g*16 + k] * ew1[(160 + k)*128 + j];
        d_Rg[g*128 + TAU16(j)] = acc;
    }
}

// ---------------- K1: persistent precompute P, Q, Ms via fp16 mma (+gcnt) ----------------
#define PRE_SMEM (14784 * 4)
__global__ void __launch_bounds__(512, 1)
k_pre(const float* __restrict__ x, const float* __restrict__ ew1,
      const float* __restrict__ n1w1, const float* __restrict__ n1b1,
      const int* __restrict__ batch) {
    extern __shared__ float sm[];
    uint32_t* sWa  = (uint32_t*)sm;
    uint32_t* sWb  = (uint32_t*)(sm + 4096);
    uint32_t* sWm  = (uint32_t*)(sm + 8192);
    uint32_t* sX   = (uint32_t*)(sm + 12288);     // [n*36]
    float*    sBmt = sm + 14592;
    int*      sBat = (int*)(sm + 14720);

    int tid = threadIdx.x, lane = tid & 31, w = tid >> 5;
    int wm = w & 3, wn = w >> 2;
    int g = lane >> 2, tig = lane & 3;
    int e1 = wm*16 + g, e2 = e1 + 8;

    for (int i = tid; i < 4096; i += 512) {
        int q = i & 3, ln = (i >> 2) & 31, pr = (i >> 7) & 1;
        int s = (i >> 8) & 3, wn_ = (i >> 10) & 3;
        int gg = ln >> 2, tt = ln & 3;
        int nt = pr*2 + (q >> 1), hb = q & 1;
        int n = (wn_*4 + nt)*8 + gg;
        int k0 = s*16 + 2*tt + hb*8;
        sWa[i] = f2h2(ew1[k0*128 + n],        ew1[(k0 + 1)*128 + n]);
        sWb[i] = f2h2(ew1[(64 + k0)*128 + n], ew1[(64 + k0 + 1)*128 + n]);
        sWm[i] = f2h2(n1w1[k0*128 + n],       n1w1[(k0 + 1)*128 + n]);
    }
    if (tid < 128) sBmt[TAU16(tid)] = n1b1[tid];

    for (int t = blockIdx.x; t < NTILEN; t += gridDim.x) {
        __syncthreads();
        int n0 = t * 64;
        if (tid < 64) {
            int n = n0 + tid;
            int b = (n < NN) ? batch[n] : 0;
            sBat[tid] = b;
            if (n < NN) red_add_f(&d_gcnt[b], 1.f);
        }
        for (int i = tid; i < 64*32; i += 512) {
            int row = i >> 5, c2 = i & 31;
            int n = n0 + row;
            float a = 0.f, b = 0.f;
            if (n < NN) { a = x[(size_t)n*64 + 2*c2]; b = x[(size_t)n*64 + 2*c2 + 1]; }
            sX[row*36 + c2] = f2h2(a, b);
        }
        __syncthreads();

        for (int which = 0; which < 3; which++) {
            const uint32_t* W = (which == 0) ? sWa : (which == 1) ? sWb : sWm;
            float acc[4][4];
            #pragma unroll
            for (int nt = 0; nt < 4; nt++)
                #pragma unroll
                for (int j = 0; j < 4; j++) acc[nt][j] = 0.f;
            #pragma unroll
            for (int s = 0; s < 4; s++) {
                uint32_t a[4];
                a[0] = sX[e1*36 + s*8 + tig];
                a[1] = sX[e2*36 + s*8 + tig];
                a[2] = sX[e1*36 + s*8 + tig + 4];
                a[3] = sX[e2*36 + s*8 + tig + 4];
                uint4 b01 = *(const uint4*)&W[((wn*4 + s)*2 + 0)*128 + lane*4];
                uint4 b23 = *(const uint4*)&W[((wn*4 + s)*2 + 1)*128 + lane*4];
                mma16(acc[0], a, b01.x, b01.y);
                mma16(acc[1], a, b01.z, b01.w);
                mma16(acc[2], a, b23.x, b23.y);
                mma16(acc[3], a, b23.z, b23.w);
            }
            float* dst = (which == 0) ? d_P : (which == 1) ? d_Q : d_Ms;
            int pos = wn*32 + tig*4;
            #pragma unroll
            for (int half = 0; half < 2; half++) {
                int e = half ? e2 : e1;
                int n = n0 + e;
                if (n >= NN) continue;
                int o = half ? 2 : 0;
                float4 v0 = make_float4(acc[0][o], acc[0][o+1], acc[1][o], acc[1][o+1]);
                float4 v1 = make_float4(acc[2][o], acc[2][o+1], acc[3][o], acc[3][o+1]);
                if (which == 0) {
                    const float4* rg = (const float4*)&d_Rg[(size_t)sBat[e]*128 + pos];
                    float4 r0 = rg[0], r1 = rg[4];
                    v0.x += r0.x; v0.y += r0.y; v0.z += r0.z; v0.w += r0.w;
                    v1.x += r1.x; v1.y += r1.y; v1.z += r1.z; v1.w += r1.w;
                } else if (which == 2) {
                    const float4* bm = (const float4*)&sBmt[pos];
                    float4 r0 = bm[0], r1 = bm[4];
                    v0.x += r0.x; v0.y += r0.y; v0.z += r0.z; v0.w += r0.w;
                    v1.x += r1.x; v1.y += r1.y; v1.z += r1.z; v1.w += r1.w;
                }
                *(float4*)&dst[(size_t)n*128 + pos]      = v0;
                *(float4*)&dst[(size_t)n*128 + pos + 16] = v1;
            }
        }
    }
}

// ================= K2: merged edge pipeline — 8 independent 128-thr groups per CTA =================
// words: sW1p 2048 | sW2p 4096 | sW3p 4096 | sW4p 8192 | sEA 2560 | sEN 4608 |
//        sH1 8704 | sH2 8704 | sB2 64 | sB4 128 | idx 256  = 43456 words (173.8 KB)
#define S2_SMEM (43456 * 4)
__global__ void __launch_bounds__(1024, 1)
k2(const float* __restrict__ ea, const float* __restrict__ ew1,
   const float* __restrict__ ew2, const float* __restrict__ eb2,
   const float* __restrict__ n1w1, const float* __restrict__ n1w2,
   const float* __restrict__ n1b2,
   const int* __restrict__ ei, float* __restrict__ outE) {
    extern __shared__ float sm[];
    uint32_t* sW1p = (uint32_t*)sm;               // 2048
    uint32_t* sW2p = (uint32_t*)(sm + 2048);      // 4096
    uint32_t* sW3p = (uint32_t*)(sm + 6144);      // 4096
    uint32_t* sW4p = (uint32_t*)(sm + 10240);     // 8192
    uint32_t* sEA  = (uint32_t*)(sm + 18432);     // 2560  [e*20]
    uint32_t* sEN  = (uint32_t*)(sm + 20992);     // 4608  [e*36]
    uint32_t* sH1  = (uint32_t*)(sm + 25600);     // 8704  [e*68]
    uint32_t* sH2  = (uint32_t*)(sm + 34304);     // 8704  [e*68]
    float*    sB2  = sm + 43008;
    float*    sB4  = sm + 43072;
    int* sRow = (int*)(sm + 43200);
    int* sCol = sRow + 128;

    int tid = threadIdx.x, lane = tid & 31, w = tid >> 5;
    int wm = w & 7, wn = w >> 3;
    int g = lane >> 2, tig = lane & 3;
    int e1 = wm*16 + g, e2 = e1 + 8;          // smem rows owned by group wm
    int gt = wn*32 + lane;                     // 0..127 within group

    // ---- one-time weight staging (block-wide) ----
    for (int i = tid; i < 2048; i += 1024) {
        int q = i & 3, ln = (i >> 2) & 31, pr = (i >> 7) & 1;
        int s = (i >> 8) & 1, wn_ = (i >> 9) & 3;
        int gg = ln >> 2, tt = ln & 3;
        int nt = pr*2 + (q >> 1), hb = q & 1;
        int n = (wn_*4 + nt)*8 + gg;
        int k0 = s*16 + 2*tt + hb*8;
        sW1p[i] = f2h2(ew1[(128 + k0)*128 + n], ew1[(128 + k0 + 1)*128 + n]);
    }
    for (int i = tid; i < 4096; i += 1024) {
        int q = i & 3, ln = (i >> 2) & 31;
        int s = (i >> 7) & 7, wn_ = (i >> 10) & 3;
        int gg = ln >> 2, tt = ln & 3;
        int nt = q >> 1, hb = q & 1;
        int n = (wn_*2 + nt)*8 + gg;
        int k0 = s*16 + 2*tt + hb*8;
        sW2p[i] = f2h2(ew2[k0*64 + n], ew2[(k0 + 1)*64 + n]);
    }
    for (int i = tid; i < 4096; i += 1024) {
        int q = i & 3, ln = (i >> 2) & 31, pr = (i >> 7) & 1;
        int s = (i >> 8) & 3, wn_ = (i >> 10) & 3;
        int gg = ln >> 2, tt = ln & 3;
        int nt = pr*2 + (q >> 1), hb = q & 1;
        int n = (wn_*4 + nt)*8 + gg;
        int k0 = s*16 + 2*tt + hb*8;
        sW3p[i] = f2h2(n1w1[(64 + k0)*128 + n], n1w1[(64 + k0 + 1)*128 + n]);
    }
    for (int i = tid; i < 8192; i += 1024) {
        int q = i & 3, ln = (i >> 2) & 31, pr = (i >> 7) & 1;
        int s = (i >> 8) & 7, wn_ = (i >> 11) & 3;
        int gg = ln >> 2, tt = ln & 3;
        int nt = pr*2 + (q >> 1), hb = q & 1;
        int n = (wn_*4 + nt)*8 + gg;
        int k0 = s*16 + 2*tt + hb*8;
        sW4p[i] = f2h2(n1w2[k0*128 + n], n1w2[(k0 + 1)*128 + n]);
    }
    if (tid < 64)  sB2[tid] = eb2[tid];
    if (tid < 128) sB4[tid] = n1b2[tid];
    __syncthreads();   // weights visible to all groups; last block-wide barrier

    // ---- per-group independent tile stream (16 edges per tile) ----
    for (int t = blockIdx.x*8 + wm; t < NTILE16; t += gridDim.x*8) {
        gbar(wm);      // previous-tile group reads done
        int e0 = t * 16;
        if (gt < 16) {
            int rr = ei[e0 + gt], cc = ei[NE + e0 + gt];
            sRow[wm*16 + gt] = rr; sCol[wm*16 + gt] = cc;
            red_add_f(&d_deg[cc], 1.f);
        }
        {   // stage EA: 16 edges x 32 floats; thread gt handles edge gt>>3, chunk gt&7
            int el = gt >> 3, ch = gt & 7;
            float4 v = *(const float4*)&ea[(size_t)(e0 + el)*32 + ch*4];
            *(uint2*)&sEA[(wm*16 + el)*20 + ch*2] = make_uint2(f2h2(v.x, v.y), f2h2(v.z, v.w));
        }
        gbar(wm);

        int r1 = sRow[e1], cc1 = sCol[e1];
        int r2 = sRow[e2], cc2 = sCol[e2];

        // GEMM1: H1 = relu(PR[row] + Q[col] + EA @ W1c)
        float acc[4][4];
        {
            const float4* P1 = (const float4*)&d_P[(size_t)r1*128 + wn*32 + tig*4];
            const float4* Q1 = (const float4*)&d_Q[(size_t)cc1*128 + wn*32 + tig*4];
            const float4* P2 = (const float4*)&d_P[(size_t)r2*128 + wn*32 + tig*4];
            const float4* Q2 = (const float4*)&d_Q[(size_t)cc2*128 + wn*32 + tig*4];
            float4 a0 = P1[0], b0 = Q1[0], a1 = P1[4], b1 = Q1[4];
            float4 c0 = P2[0], d0 = Q2[0], c1 = P2[4], d1 = Q2[4];
            acc[0][0] = a0.x + b0.x; acc[0][1] = a0.y + b0.y;
            acc[1][0] = a0.z + b0.z; acc[1][1] = a0.w + b0.w;
            acc[0][2] = c0.x + d0.x; acc[0][3] = c0.y + d0.y;
            acc[1][2] = c0.z + d0.z; acc[1][3] = c0.w + d0.w;
            acc[2][0] = a1.x + b1.x; acc[2][1] = a1.y + b1.y;
            acc[3][0] = a1.z + b1.z; acc[3][1] = a1.w + b1.w;
            acc[2][2] = c1.x + d1.x; acc[2][3] = c1.y + d1.y;
            acc[3][2] = c1.z + d1.z; acc[3][3] = c1.w + d1.w;
        }
        #pragma unroll
        for (int s = 0; s < 2; s++) {
            uint32_t a[4];
            a[0] = sEA[e1*20 + s*8 + tig];
            a[1] = sEA[e2*20 + s*8 + tig];
            a[2] = sEA[e1*20 + s*8 + tig + 4];
            a[3] = sEA[e2*20 + s*8 + tig + 4];
            uint4 b01 = *(const uint4*)&sW1p[((wn*2 + s)*2 + 0)*128 + lane*4];
            uint4 b23 = *(const uint4*)&sW1p[((wn*2 + s)*2 + 1)*128 + lane*4];
            mma16(acc[0], a, b01.x, b01.y);
            mma16(acc[1], a, b01.z, b01.w);
            mma16(acc[2], a, b23.x, b23.y);
            mma16(acc[3], a, b23.z, b23.w);
        }
        #pragma unroll
        for (int nt = 0; nt < 4; nt++) {
            int cu = wn*16 + nt*4 + tig;
            sH1[e1*68 + cu] = f2h2(fmaxf(acc[nt][0], 0.f), fmaxf(acc[nt][1], 0.f));
            sH1[e2*68 + cu] = f2h2(fmaxf(acc[nt][2], 0.f), fmaxf(acc[nt][3], 0.f));
        }
        gbar(wm);

        // GEMM2: EN = H1 @ W2 + b2 → outE + sEN
        float acc2[2][4];
        #pragma unroll
        for (int nt = 0; nt < 2; nt++) {
            int c = wn*16 + nt*8 + tig*2;
            acc2[nt][0] = sB2[c]; acc2[nt][1] = sB2[c+1];
            acc2[nt][2] = sB2[c]; acc2[nt][3] = sB2[c+1];
        }
        #pragma unroll
        for (int s = 0; s < 8; s++) {
            uint32_t a[4];
            a[0] = sH1[e1*68 + s*8 + tig];
            a[1] = sH1[e2*68 + s*8 + tig];
            a[2] = sH1[e1*68 + s*8 + tig + 4];
            a[3] = sH1[e2*68 + s*8 + tig + 4];
            uint4 b = *(const uint4*)&sW2p[(wn*8 + s)*128 + lane*4];
            mma16(acc2[0], a, b.x, b.y);
            mma16(acc2[1], a, b.z, b.w);
        }
        #pragma unroll
        for (int nt = 0; nt < 2; nt++) {
            int c = wn*16 + nt*8 + tig*2;
            *(float2*)&outE[(size_t)(e0 + g)*64 + c]     = make_float2(acc2[nt][0], acc2[nt][1]);
            *(float2*)&outE[(size_t)(e0 + g + 8)*64 + c] = make_float2(acc2[nt][2], acc2[nt][3]);
            int cu = wn*8 + nt*4 + tig;
            sEN[e1*36 + cu] = f2h2(acc2[nt][0], acc2[nt][1]);
            sEN[e2*36 + cu] = f2h2(acc2[nt][2], acc2[nt][3]);
        }
        gbar(wm);

        // GEMM3: H2 = relu(Ms[row] + EN @ W3)
        {
            const float4* M1 = (const float4*)&d_Ms[(size_t)r1*128 + wn*32 + tig*4];
            const float4* M2 = (const float4*)&d_Ms[(size_t)r2*128 + wn*32 + tig*4];
            float4 a0 = M1[0], a1 = M1[4], b0 = M2[0], b1 = M2[4];
            acc[0][0] = a0.x; acc[0][1] = a0.y; acc[1][0] = a0.z; acc[1][1] = a0.w;
            acc[0][2] = b0.x; acc[0][3] = b0.y; acc[1][2] = b0.z; acc[1][3] = b0.w;
            acc[2][0] = a1.x; acc[2][1] = a1.y; acc[3][0] = a1.z; acc[3][1] = a1.w;
            acc[2][2] = b1.x; acc[2][3] = b1.y; acc[3][2] = b1.z; acc[3][3] = b1.w;
        }
        #pragma unroll
        for (int s = 0; s < 4; s++) {
            uint32_t a[4];
            a[0] = sEN[e1*36 + s*8 + tig];
            a[1] = sEN[e2*36 + s*8 + tig];
            a[2] = sEN[e1*36 + s*8 + tig + 4];
            a[3] = sEN[e2*36 + s*8 + tig + 4];
            uint4 b01 = *(const uint4*)&sW3p[((wn*4 + s)*2 + 0)*128 + lane*4];
            uint4 b23 = *(const uint4*)&sW3p[((wn*4 + s)*2 + 1)*128 + lane*4];
            mma16(acc[0], a, b01.x, b01.y);
            mma16(acc[1], a, b01.z, b01.w);
            mma16(acc[2], a, b23.x, b23.y);
            mma16(acc[3], a, b23.z, b23.w);
        }
        #pragma unroll
        for (int nt = 0; nt < 4; nt++) {
            int cu = wn*16 + nt*4 + tig;
            sH2[e1*68 + cu] = f2h2(fmaxf(acc[nt][0], 0.f), fmaxf(acc[nt][1], 0.f));
            sH2[e2*68 + cu] = f2h2(fmaxf(acc[nt][2], 0.f), fmaxf(acc[nt][3], 0.f));
        }
        gbar(wm);

        // GEMM4: m = H2 @ W4 + b4 → TAU16 v4 scatter
        float acc4[4][4];
        #pragma unroll
        for (int nt = 0; nt < 4; nt++) {
            int c = wn*32 + nt*8 + tig*2;
            acc4[nt][0] = sB4[c]; acc4[nt][1] = sB4[c+1];
            acc4[nt][2] = sB4[c]; acc4[nt][3] = sB4[c+1];
        }
        #pragma unroll
        for (int s = 0; s < 8; s++) {
            uint32_t a[4];
            a[0] = sH2[e1*68 + s*8 + tig];
            a[1] = sH2[e2*68 + s*8 + tig];
            a[2] = sH2[e1*68 + s*8 + tig + 4];
            a[3] = sH2[e2*68 + s*8 + tig + 4];
            uint4 b01 = *(const uint4*)&sW4p[((wn*8 + s)*2 + 0)*128 + lane*4];
            uint4 b23 = *(const uint4*)&sW4p[((wn*8 + s)*2 + 1)*128 + lane*4];
            mma16(acc4[0], a, b01.x, b01.y);
            mma16(acc4[1], a, b01.z, b01.w);
            mma16(acc4[2], a, b23.x, b23.y);
            mma16(acc4[3], a, b23.z, b23.w);
        }
        {
            float* p1 = &d_agg[(size_t)cc1*128 + wn*32 + tig*4];
            red_add_v4f(p1,      acc4[0][0], acc4[0][1], acc4[1][0], acc4[1][1]);
            red_add_v4f(p1 + 16, acc4[2][0], acc4[2][1], acc4[3][0], acc4[3][1]);
            float* p2 = &d_agg[(size_t)cc2*128 + wn*32 + tig*4];
            red_add_v4f(p2,      acc4[0][2], acc4[0][3], acc4[1][2], acc4[1][3]);
            red_add_v4f(p2 + 16, acc4[2][2], acc4[2][3], acc4[3][2], acc4[3][3]);
        }
    }
}

// ---------------- K3: persistent node MLP2 + pooling via fp16 mma ----------------
#define NODE_SMEM (30528 * 4)
__global__ void __launch_bounds__(512, 1)
k_node(const float* __restrict__ x, const float* __restrict__ u,
       const float* __restrict__ n2w1, const float* __restrict__ n2b1,
       const float* __restrict__ n2w2, const float* __restrict__ n2b2,
       const int* __restrict__ batch, float* __restrict__ outX) {
    extern __shared__ float sm[];
    uint32_t* sW1p = (uint32_t*)sm;               // 13312
    uint32_t* sW2p = (uint32_t*)(sm + 13312);     // 4096
    uint32_t* sIn  = (uint32_t*)(sm + 17408);     // 8448 [n*132]
    uint32_t* sH   = (uint32_t*)(sm + 25856);     // 4352 [n*68]
    float*    sB1  = sm + 30208;
    float*    sB2  = sm + 30336;
    float*    sInv = sm + 30400;
    int*      sBat = (int*)(sm + 30464);

    int tid = threadIdx.x, lane = tid & 31, w = tid >> 5;
    int wm = w & 3, wn = w >> 2;
    int g = lane >> 2, tig = lane & 3;
    int e1 = wm*16 + g, e2 = e1 + 8;

    for (int i = tid; i < 13312; i += 512) {
        int q = i & 3, ln = (i >> 2) & 31, pr = (i >> 7) & 1;
        int blk = i >> 8;
        int s = blk % 13, wn_ = blk / 13;
        int gg = ln >> 2, tt = ln & 3;
        int nt = pr*2 + (q >> 1), hb = q & 1;
        int n = (wn_*4 + nt)*8 + gg;
        int k0 = s*16 + 2*tt + hb*8;
        sW1p[i] = f2h2(n2w1[k0*128 + n], n2w1[(k0 + 1)*128 + n]);
    }
    for (int i = tid; i < 4096; i += 512) {
        int q = i & 3, ln = (i >> 2) & 31;
        int s = (i >> 7) & 7, wn_ = (i >> 10) & 3;
        int gg = ln >> 2, tt = ln & 3;
        int nt = q >> 1, hb = q & 1;
        int n = (wn_*2 + nt)*8 + gg;
        int k0 = s*16 + 2*tt + hb*8;
        sW2p[i] = f2h2(n2w2[k0*64 + n], n2w2[(k0 + 1)*64 + n]);
    }
    if (tid < 128) sB1[tid] = n2b1[tid];
    if (tid < 64)  sB2[tid] = n2b2[tid];

    for (int t = blockIdx.x; t < NTILEN; t += gridDim.x) {
        __syncthreads();
        int n0 = t * 64;
        if (tid < 64) {
            int n = n0 + tid;
            if (n < NN) { sBat[tid] = batch[n]; sInv[tid] = 1.f / fmaxf(d_deg[n], 1.f); }
            else        { sBat[tid] = 0;        sInv[tid] = 0.f; }
        }
        __syncthreads();

        for (int i = tid; i < 64*104; i += 512) {
            int row = i / 104, c2 = i % 104;
            int n = n0 + row;
            float a = 0.f, b = 0.f;
            if (n < NN) {
                int c = 2*c2;
                #pragma unroll
                for (int j = 0; j < 2; j++) {
                    int cc = c + j;
                    float v;
                    if (cc < 64)       v = x[(size_t)n*64 + cc];
                    else if (cc < 192) v = d_agg[(size_t)n*128 + TAU16(cc - 64)] * sInv[row];
                    else               v = u[sBat[row]*16 + (cc - 192)];
                    if (j == 0) a = v; else b = v;
                }
            }
            sIn[row*132 + c2] = f2h2(a, b);
        }
        __syncthreads();

        float acc[4][4];
        #pragma unroll
        for (int nt = 0; nt < 4; nt++) {
            int c = wn*32 + nt*8 + tig*2;
            acc[nt][0] = sB1[c]; acc[nt][1] = sB1[c+1];
            acc[nt][2] = sB1[c]; acc[nt][3] = sB1[c+1];
        }
        for (int s = 0; s < 13; s++) {
            uint32_t a[4];
            a[0] = sIn[e1*132 + s*8 + tig];
            a[1] = sIn[e2*132 + s*8 + tig];
            a[2] = sIn[e1*132 + s*8 + tig + 4];
            a[3] = sIn[e2*132 + s*8 + tig + 4];
            uint4 b01 = *(const uint4*)&sW1p[((wn*13 + s)*2 + 0)*128 + lane*4];
            uint4 b23 = *(const uint4*)&sW1p[((wn*13 + s)*2 + 1)*128 + lane*4];
            mma16(acc[0], a, b01.x, b01.y);
            mma16(acc[1], a, b01.z, b01.w);
            mma16(acc[2], a, b23.x, b23.y);
            mma16(acc[3], a, b23.z, b23.w);
        }
        #pragma unroll
        for (int nt = 0; nt < 4; nt++) {
            int cu = wn*16 + nt*4 + tig;
            sH[e1*68 + cu] = f2h2(fmaxf(acc[nt][0], 0.f), fmaxf(acc[nt][1], 0.f));
            sH[e2*68 + cu] = f2h2(fmaxf(acc[nt][2], 0.f), fmaxf(acc[nt][3], 0.f));
        }
        __syncthreads();

        float acc2[2][4];
        #pragma unroll
        for (int nt = 0; nt < 2; nt++) {
            int c = wn*16 + nt*8 + tig*2;
            acc2[nt][0] = sB2[c]; acc2[nt][1] = sB2[c+1];
            acc2[nt][2] = sB2[c]; acc2[nt][3] = sB2[c+1];
        }
        #pragma unroll
        for (int s = 0; s < 8; s++) {
            uint32_t a[4];
            a[0] = sH[e1*68 + s*8 + tig];
            a[1] = sH[e2*68 + s*8 + tig];
            a[2] = sH[e1*68 + s*8 + tig + 4];
            a[3] = sH[e2*68 + s*8 + tig + 4];
            uint4 b = *(const uint4*)&sW2p[(wn*8 + s)*128 + lane*4];
            mma16(acc2[0], a, b.x, b.y);
            mma16(acc2[1], a, b.z, b.w);
        }
        #pragma unroll
        for (int nt = 0; nt < 2; nt++) {
            int c = wn*16 + nt*8 + tig*2;
            int n1n = n0 + e1, n2n = n0 + e2;
            if (n1n < NN) {
                *(float2*)&outX[(size_t)n1n*64 + c] = make_float2(acc2[nt][0], acc2[nt][1]);
                red_add_f(&d_gsum[sBat[e1]*64 + c],     acc2[nt][0]);
                red_add_f(&d_gsum[sBat[e1]*64 + c + 1], acc2[nt][1]);
            }
            if (n2n < NN) {
                *(float2*)&outX[(size_t)n2n*64 + c] = make_float2(acc2[nt][2], acc2[nt][3]);
                red_add_f(&d_gsum[sBat[e2]*64 + c],     acc2[nt][2]);
                red_add_f(&d_gsum[sBat[e2]*64 + c + 1], acc2[nt][3]);
            }
        }
    }
}

// ---------------- K4: global MLP ----------------
__global__ void k_glob(const float* __restrict__ u,
                       const float* __restrict__ gw1, const float* __restrict__ gb1,
                       const float* __restrict__ gw2, const float* __restrict__ gb2,
                       float* __restrict__ outU) {
    __shared__ float sin[80];
    __shared__ float sh[128];
    int g = blockIdx.x, tid = threadIdx.x;
    if (tid < 16) sin[tid] = u[g*16 + tid];
    if (tid < 64) {
        float c = fmaxf(d_gcnt[g], 1.f);
        sin[16 + tid] = d_gsum[g*64 + tid] / c;
    }
    __syncthreads();
    float acc = gb1[tid];
    #pragma unroll 8
    for (int k = 0; k < 80; k++) acc += sin[k] * gw1[k*128 + tid];
    sh[tid] = fmaxf(acc, 0.f);
    __syncthreads();
    if (tid < 32) {
        float a2 = gb2[tid];
        #pragma unroll 8
        for (int k = 0; k < 128; k++) a2 += sh[k] * gw2[k*32 + tid];
        outU[g*32 + tid] = a2;
    }
}

// ---------------- launch ----------------
extern "C" void kernel_launch(void* const* d_in, const int* in_sizes, int n_in,
                              void* d_out, int out_size) {
    const float* x     = (const float*)d_in[0];
    const float* ea    = (const float*)d_in[1];
    const float* u     = (const float*)d_in[2];
    const float* ew1   = (const float*)d_in[3];
    const float* eb1   = (const float*)d_in[4];
    const float* ew2   = (const float*)d_in[5];
    const float* eb2   = (const float*)d_in[6];
    const float* n1w1  = (const float*)d_in[7];
    const float* n1b1  = (const float*)d_in[8];
    const float* n1w2  = (const float*)d_in[9];
    const float* n1b2  = (const float*)d_in[10];
    const float* n2w1  = (const float*)d_in[11];
    const float* n2b1  = (const float*)d_in[12];
    const float* n2w2  = (const float*)d_in[13];
    const float* n2b2  = (const float*)d_in[14];
    const float* gw1   = (const float*)d_in[15];
    const float* gb1   = (const float*)d_in[16];
    const float* gw2   = (const float*)d_in[17];
    const float* gb2   = (const float*)d_in[18];
    const int*   ei    = (const int*)d_in[19];
    const int*   batch = (const int*)d_in[20];

    float* out  = (float*)d_out;
    float* outX = out;
    float* outE = out + (size_t)NN*64;
    float* outU = out + (size_t)NN*64 + (size_t)NE*64;

    cudaFuncSetAttribute(k_pre,  cudaFuncAttributeMaxDynamicSharedMemorySize, PRE_SMEM);
    cudaFuncSetAttribute(k2,     cudaFuncAttributeMaxDynamicSharedMemorySize, S2_SMEM);
    cudaFuncSetAttribute(k_node, cudaFuncAttributeMaxDynamicSharedMemorySize, NODE_SMEM);

    k_zero<<<256, 256>>>();
    k_rg<<<(NG*128 + 255)/256, 256>>>(u, ew1, eb1);
    k_pre<<<PGRID, 512, PRE_SMEM>>>(x, ew1, n1w1, n1b1, batch);
    k2<<<PGRID, 1024, S2_SMEM>>>(ea, ew1, ew2, eb2, n1w1, n1w2, n1b2, ei, outE);
    k_node<<<PGRID, 512, NODE_SMEM>>>(x, u, n2w1, n2b1, n2w2, n2b2, batch, outX);
    k_glob<<<NG, 128>>>(u, gw1, gb1, gw2, gb2, outU);
}